// round 1
// baseline (speedup 1.0000x reference)
#include <cuda_runtime.h>
#include <math.h>

// Problem constants
#define BATCH 8
#define SEQ   1024
#define CH    768
#define C3    2304      // 3*CH
#define C6    4608      // 6*CH
#define HFDIM 3072      // 4*CH
#define NHEAD 12
#define HDIM  64
#define ROWS  8192      // BATCH*SEQ

// ---------------------------------------------------------------------------
// Scratch (device globals — no allocation allowed)
// ---------------------------------------------------------------------------
__device__ float g_ada[BATCH * C6];                       // 147 KB
__device__ float g_h  [(size_t)ROWS * CH];                // 25 MB (modulated LN out)
__device__ float g_qkv[(size_t)ROWS * C3];                // 75.5 MB
__device__ float g_att[(size_t)ROWS * CH];                // 25 MB (attention out)
__device__ float g_x1 [(size_t)ROWS * CH];                // 25 MB (x after MSA residual)
__device__ float g_mlp[(size_t)ROWS * HFDIM];             // 100 MB (MLP hidden)

// ---------------------------------------------------------------------------
// 1) ada = silu(c) @ ada_w^T + ada_b      [8, 4608]
//    grid (4608/8, 8), block 256: one warp per output, warp-reduced dot.
// ---------------------------------------------------------------------------
__global__ __launch_bounds__(256) void ada_kernel(
    const float* __restrict__ c,
    const float* __restrict__ ada_w,
    const float* __restrict__ ada_b)
{
    __shared__ float sc[CH];
    int b = blockIdx.y;
    for (int k = threadIdx.x; k < CH; k += 256) {
        float v = c[b * CH + k];
        sc[k] = v / (1.f + expf(-v));     // silu
    }
    __syncthreads();

    int warp = threadIdx.x >> 5, lane = threadIdx.x & 31;
    int j = blockIdx.x * 8 + warp;
    const float* w = ada_w + (size_t)j * CH;
    float s = 0.f;
    for (int k = lane; k < CH; k += 32) s += sc[k] * w[k];
#pragma unroll
    for (int o = 16; o; o >>= 1) s += __shfl_xor_sync(0xffffffffu, s, o);
    if (lane == 0) g_ada[b * C6 + j] = s + ada_b[j];
}

// ---------------------------------------------------------------------------
// 2) h = LN(x) * (1 + sc[b]) + sh[b]      one block per row (8192 blocks)
// ---------------------------------------------------------------------------
__global__ __launch_bounds__(256) void ln_mod_kernel(
    const float* __restrict__ x, int sh_off, int sc_off,
    float* __restrict__ out)
{
    int r = blockIdx.x;
    int b = r >> 10;
    const float* xr = x + (size_t)r * CH;
    int t = threadIdx.x;

    float v[3];
    float s = 0.f, ss = 0.f;
#pragma unroll
    for (int u = 0; u < 3; u++) {
        float w = xr[t + u * 256];
        v[u] = w; s += w; ss += w * w;
    }
#pragma unroll
    for (int o = 16; o; o >>= 1) {
        s  += __shfl_xor_sync(0xffffffffu, s,  o);
        ss += __shfl_xor_sync(0xffffffffu, ss, o);
    }
    __shared__ float rs[8], rss[8];
    __shared__ float smu, srv;
    int warp = t >> 5;
    if ((t & 31) == 0) { rs[warp] = s; rss[warp] = ss; }
    __syncthreads();
    if (t == 0) {
        float ts = 0.f, tss = 0.f;
#pragma unroll
        for (int i = 0; i < 8; i++) { ts += rs[i]; tss += rss[i]; }
        float mu  = ts  * (1.f / (float)CH);
        float var = tss * (1.f / (float)CH) - mu * mu;
        smu = mu;
        srv = rsqrtf(var + 1e-6f);
    }
    __syncthreads();
    float mu = smu, rinv = srv;
    const float* sh  = g_ada + b * C6 + sh_off;
    const float* scm = g_ada + b * C6 + sc_off;
    float* orow = out + (size_t)r * CH;
#pragma unroll
    for (int u = 0; u < 3; u++) {
        int i = t + u * 256;
        orow[i] = (v[u] - mu) * rinv * (1.f + scm[i]) + sh[i];
    }
}

// ---------------------------------------------------------------------------
// 3) Generic GEMM: C[M,Nc] = A[M,K] @ W[Nc,K]^T + bias, 128x128x16 tile,
//    256 threads, 8x8 per-thread microtile.
//    EPI: 0 = bias only; 1 = bias + exact GELU; 2 = resid + gate * (bias+acc)
// ---------------------------------------------------------------------------
template <int EPI>
__global__ __launch_bounds__(256) void gemm_kernel(
    const float* __restrict__ A, const float* __restrict__ W,
    const float* __restrict__ bias,
    const float* __restrict__ resid, const float* __restrict__ gate,
    float* __restrict__ Cout, int M, int Nc, int K)
{
    __shared__ float As[16][128];
    __shared__ float Bs[16][128];

    int t  = threadIdx.x;
    int m0 = blockIdx.y * 128, n0 = blockIdx.x * 128;
    int ty = t >> 4, tx = t & 15;
    int lr = t >> 2;             // 0..63
    int lc = (t & 3) << 2;       // 0,4,8,12

    const float* Ap = A + (size_t)(m0 + lr) * K + lc;
    const float* Wp = W + (size_t)(n0 + lr) * K + lc;

    float acc[8][8];
#pragma unroll
    for (int i = 0; i < 8; i++)
#pragma unroll
        for (int j = 0; j < 8; j++) acc[i][j] = 0.f;

    for (int k0 = 0; k0 < K; k0 += 16) {
        float4 a0 = *(const float4*)(Ap + k0);
        float4 a1 = *(const float4*)(Ap + (size_t)64 * K + k0);
        float4 b0 = *(const float4*)(Wp + k0);
        float4 b1 = *(const float4*)(Wp + (size_t)64 * K + k0);

        As[lc + 0][lr]      = a0.x; As[lc + 1][lr]      = a0.y;
        As[lc + 2][lr]      = a0.z; As[lc + 3][lr]      = a0.w;
        As[lc + 0][lr + 64] = a1.x; As[lc + 1][lr + 64] = a1.y;
        As[lc + 2][lr + 64] = a1.z; As[lc + 3][lr + 64] = a1.w;
        Bs[lc + 0][lr]      = b0.x; Bs[lc + 1][lr]      = b0.y;
        Bs[lc + 2][lr]      = b0.z; Bs[lc + 3][lr]      = b0.w;
        Bs[lc + 0][lr + 64] = b1.x; Bs[lc + 1][lr + 64] = b1.y;
        Bs[lc + 2][lr + 64] = b1.z; Bs[lc + 3][lr + 64] = b1.w;
        __syncthreads();

#pragma unroll
        for (int k = 0; k < 16; k++) {
            float a[8], bb[8];
            *(float4*)&a[0]  = *(const float4*)&As[k][ty * 8];
            *(float4*)&a[4]  = *(const float4*)&As[k][ty * 8 + 4];
            *(float4*)&bb[0] = *(const float4*)&Bs[k][tx * 8];
            *(float4*)&bb[4] = *(const float4*)&Bs[k][tx * 8 + 4];
#pragma unroll
            for (int i = 0; i < 8; i++)
#pragma unroll
                for (int j = 0; j < 8; j++)
                    acc[i][j] = fmaf(a[i], bb[j], acc[i][j]);
        }
        __syncthreads();
    }

    int bidx = m0 >> 10;  // batch index (block never straddles a batch: 1024 % 128 == 0)
#pragma unroll
    for (int i = 0; i < 8; i++) {
        int m = m0 + ty * 8 + i;
#pragma unroll
        for (int j = 0; j < 8; j += 4) {
            float4 o;
            float* ov = (float*)&o;
#pragma unroll
            for (int w = 0; w < 4; w++) {
                int n = n0 + tx * 8 + j + w;
                float v = acc[i][j + w] + bias[n];
                if (EPI == 1) v = 0.5f * v * (1.f + erff(v * 0.70710678118654752f));
                if (EPI == 2) v = resid[(size_t)m * Nc + n] + gate[bidx * C6 + n] * v;
                ov[w] = v;
            }
            *(float4*)&Cout[(size_t)m * Nc + n0 + tx * 8 + j] = o;
        }
    }
}

// ---------------------------------------------------------------------------
// 4) Attention (flash-style): grid (16, 12, 8) = (qtile, head, batch),
//    block 256 = 16x16 threads, each thread a 4x4 subtile of the 64x64 tile.
//    smem: Qs (64x64), KP (K^T then reused for P), Vs. Exactly 48 KB static.
// ---------------------------------------------------------------------------
__global__ __launch_bounds__(256) void attn_kernel(
    const float* __restrict__ qkv, float* __restrict__ out)
{
    __shared__ float Qs[64 * 64];
    __shared__ float KP[64 * 64];
    __shared__ float Vs[64 * 64];

    int b = blockIdx.z, h = blockIdx.y;
    int q0 = blockIdx.x * 64;
    int t = threadIdx.x;
    int ty = t >> 4, tx = t & 15;

    const float* base  = qkv + (size_t)(b * SEQ) * C3 + h * HDIM;
    const float* kbase = base + CH;
    const float* vbase = base + 2 * CH;

    // load Q tile (64 rows x 64 d), natural layout
#pragma unroll
    for (int u = 0; u < 4; u++) {
        int idx = t + u * 256;         // float4 index 0..1023
        int r   = idx >> 4;
        int d4  = (idx & 15) << 2;
        *(float4*)&Qs[r * 64 + d4] =
            *(const float4*)(base + (size_t)(q0 + r) * C3 + d4);
    }

    float m_i[4], l_i[4], acc[4][4];
#pragma unroll
    for (int i = 0; i < 4; i++) {
        m_i[i] = -1e30f; l_i[i] = 0.f;
#pragma unroll
        for (int j = 0; j < 4; j++) acc[i][j] = 0.f;
    }

    for (int kt = 0; kt < 16; kt++) {
        int kr0 = kt * 64;
        // load K transposed (KP[d][j]) and V (Vs[row][d])
#pragma unroll
        for (int u = 0; u < 4; u++) {
            int idx = t + u * 256;
            int r   = idx >> 4;
            int d4  = (idx & 15) << 2;
            float4 kv = *(const float4*)(kbase + (size_t)(kr0 + r) * C3 + d4);
            KP[(d4 + 0) * 64 + r] = kv.x;
            KP[(d4 + 1) * 64 + r] = kv.y;
            KP[(d4 + 2) * 64 + r] = kv.z;
            KP[(d4 + 3) * 64 + r] = kv.w;
            *(float4*)&Vs[r * 64 + d4] =
                *(const float4*)(vbase + (size_t)(kr0 + r) * C3 + d4);
        }
        __syncthreads();

        // S = scale * Q @ K^T  (4x4 per thread)
        float s[4][4];
#pragma unroll
        for (int i = 0; i < 4; i++)
#pragma unroll
            for (int j = 0; j < 4; j++) s[i][j] = 0.f;

        for (int d = 0; d < 64; d += 4) {
            float4 q4[4];
#pragma unroll
            for (int i = 0; i < 4; i++)
                q4[i] = *(const float4*)&Qs[(ty * 4 + i) * 64 + d];
#pragma unroll
            for (int dd = 0; dd < 4; dd++) {
                float4 kf = *(const float4*)&KP[(d + dd) * 64 + tx * 4];
#pragma unroll
                for (int i = 0; i < 4; i++) {
                    float qv = ((const float*)&q4[i])[dd];
                    s[i][0] = fmaf(qv, kf.x, s[i][0]);
                    s[i][1] = fmaf(qv, kf.y, s[i][1]);
                    s[i][2] = fmaf(qv, kf.z, s[i][2]);
                    s[i][3] = fmaf(qv, kf.w, s[i][3]);
                }
            }
        }
#pragma unroll
        for (int i = 0; i < 4; i++)
#pragma unroll
            for (int j = 0; j < 4; j++) s[i][j] *= 0.125f;   // 1/sqrt(64)

        // online softmax stats (row groups = 16 lanes sharing ty)
        float p[4][4], alpha[4];
#pragma unroll
        for (int i = 0; i < 4; i++) {
            float rmax = fmaxf(fmaxf(s[i][0], s[i][1]), fmaxf(s[i][2], s[i][3]));
#pragma unroll
            for (int o = 1; o < 16; o <<= 1)
                rmax = fmaxf(rmax, __shfl_xor_sync(0xffffffffu, rmax, o));
            float mnew = fmaxf(m_i[i], rmax);
            alpha[i] = __expf(m_i[i] - mnew);
            float rsum = 0.f;
#pragma unroll
            for (int j = 0; j < 4; j++) {
                p[i][j] = __expf(s[i][j] - mnew);
                rsum += p[i][j];
            }
#pragma unroll
            for (int o = 1; o < 16; o <<= 1)
                rsum += __shfl_xor_sync(0xffffffffu, rsum, o);
            l_i[i] = l_i[i] * alpha[i] + rsum;
            m_i[i] = mnew;
#pragma unroll
            for (int j = 0; j < 4; j++) acc[i][j] *= alpha[i];
        }
        __syncthreads();   // all S reads of KP done before P overwrites it

        // store P into KP (reuse)
#pragma unroll
        for (int i = 0; i < 4; i++)
            *(float4*)&KP[(ty * 4 + i) * 64 + tx * 4] =
                make_float4(p[i][0], p[i][1], p[i][2], p[i][3]);
        __syncthreads();

        // O += P @ V
        for (int kk = 0; kk < 64; kk += 4) {
            float4 p4[4];
#pragma unroll
            for (int i = 0; i < 4; i++)
                p4[i] = *(const float4*)&KP[(ty * 4 + i) * 64 + kk];
#pragma unroll
            for (int dd = 0; dd < 4; dd++) {
                float4 vf = *(const float4*)&Vs[(kk + dd) * 64 + tx * 4];
#pragma unroll
                for (int i = 0; i < 4; i++) {
                    float pv = ((const float*)&p4[i])[dd];
                    acc[i][0] = fmaf(pv, vf.x, acc[i][0]);
                    acc[i][1] = fmaf(pv, vf.y, acc[i][1]);
                    acc[i][2] = fmaf(pv, vf.z, acc[i][2]);
                    acc[i][3] = fmaf(pv, vf.w, acc[i][3]);
                }
            }
        }
        __syncthreads();   // before next tile overwrites KP/Vs
    }

    // write O / l  -> [b, n, h, d]
#pragma unroll
    for (int i = 0; i < 4; i++) {
        float inv = 1.f / l_i[i];
        float4 o = make_float4(acc[i][0] * inv, acc[i][1] * inv,
                               acc[i][2] * inv, acc[i][3] * inv);
        *(float4*)&out[(size_t)(b * SEQ + q0 + ty * 4 + i) * CH + h * HDIM + tx * 4] = o;
    }
}

// ---------------------------------------------------------------------------
// Launch
// ---------------------------------------------------------------------------
extern "C" void kernel_launch(void* const* d_in, const int* in_sizes, int n_in,
                              void* d_out, int out_size)
{
    const float* x      = (const float*)d_in[0];
    const float* c      = (const float*)d_in[1];
    const float* qkv_w  = (const float*)d_in[2];
    const float* qkv_b  = (const float*)d_in[3];
    const float* proj_w = (const float*)d_in[4];
    const float* proj_b = (const float*)d_in[5];
    const float* fc1_w  = (const float*)d_in[6];
    const float* fc1_b  = (const float*)d_in[7];
    const float* fc2_w  = (const float*)d_in[8];
    const float* fc2_b  = (const float*)d_in[9];
    const float* ada_w  = (const float*)d_in[10];
    const float* ada_b  = (const float*)d_in[11];
    float* out = (float*)d_out;

    float *p_ada, *p_h, *p_qkv, *p_att, *p_x1, *p_mlp;
    cudaGetSymbolAddress((void**)&p_ada, g_ada);
    cudaGetSymbolAddress((void**)&p_h,   g_h);
    cudaGetSymbolAddress((void**)&p_qkv, g_qkv);
    cudaGetSymbolAddress((void**)&p_att, g_att);
    cudaGetSymbolAddress((void**)&p_x1,  g_x1);
    cudaGetSymbolAddress((void**)&p_mlp, g_mlp);

    // 1) adaLN modulation parameters
    ada_kernel<<<dim3(C6 / 8, BATCH), 256>>>(c, ada_w, ada_b);

    // 2) h = modulate(LN(x), sh_msa, sc_msa)
    ln_mod_kernel<<<ROWS, 256>>>(x, 0, 768, p_h);

    // 3) qkv = h @ qkv_w^T + qkv_b      [8192, 2304]
    gemm_kernel<0><<<dim3(C3 / 128, ROWS / 128), 256>>>(
        p_h, qkv_w, qkv_b, nullptr, nullptr, p_qkv, ROWS, C3, CH);

    // 4) attention -> g_att [8192, 768]
    attn_kernel<<<dim3(SEQ / 64, NHEAD, BATCH), 256>>>(p_qkv, p_att);

    // 5) x1 = x + g_msa * (attn @ proj_w^T + proj_b)
    gemm_kernel<2><<<dim3(CH / 128, ROWS / 128), 256>>>(
        p_att, proj_w, proj_b, x, p_ada + 1536, p_x1, ROWS, CH, CH);

    // 6) h = modulate(LN(x1), sh_mlp, sc_mlp)
    ln_mod_kernel<<<ROWS, 256>>>(p_x1, 2304, 3072, p_h);

    // 7) mlp_hidden = gelu(h @ fc1_w^T + fc1_b)   [8192, 3072]
    gemm_kernel<1><<<dim3(HFDIM / 128, ROWS / 128), 256>>>(
        p_h, fc1_w, fc1_b, nullptr, nullptr, p_mlp, ROWS, HFDIM, CH);

    // 8) out = x1 + g_mlp * (mlp_hidden @ fc2_w^T + fc2_b)
    gemm_kernel<2><<<dim3(CH / 128, ROWS / 128), 256>>>(
        p_mlp, fc2_w, fc2_b, p_x1, p_ada + 3840, out, ROWS, CH, HFDIM);
}

// round 3
// speedup vs baseline: 2.1330x; 2.1330x over previous
#include <cuda_runtime.h>
#include <cuda.h>
#include <math.h>
#include <stdint.h>

// Problem constants
#define BATCH 8
#define SEQ   1024
#define CH    768
#define C3    2304      // 3*CH
#define C6    4608      // 6*CH
#define HFDIM 3072      // 4*CH
#define NHEAD 12
#define HDIM  64
#define ROWS  8192      // BATCH*SEQ

// ---------------------------------------------------------------------------
// Scratch (device globals — no allocation allowed)
// ---------------------------------------------------------------------------
__device__ float g_ada[BATCH * C6];
__device__ float g_h  [(size_t)ROWS * CH];
__device__ float g_qkv[(size_t)ROWS * C3];
__device__ float g_att[(size_t)ROWS * CH];
__device__ float g_x1 [(size_t)ROWS * CH];
__device__ float g_mlp[(size_t)ROWS * HFDIM];

// ---------------------------------------------------------------------------
// PTX helpers (sm_90-base ISA only: mbarrier + TMA + mma.sync)
// ---------------------------------------------------------------------------
__device__ __forceinline__ uint32_t smem_to_u32(const void* p) {
    uint32_t a;
    asm("{ .reg .u64 t; cvta.to.shared.u64 t, %1; cvt.u32.u64 %0, t; }"
        : "=r"(a) : "l"(p));
    return a;
}

#define MBARRIER_INIT(addr, cnt) \
    asm volatile("mbarrier.init.shared.b64 [%0], %1;" :: "r"((uint32_t)(addr)), "r"((uint32_t)(cnt)) : "memory")

#define MBARRIER_ARRIVE(addr) \
    asm volatile("mbarrier.arrive.shared.b64 _, [%0];" :: "r"((uint32_t)(addr)) : "memory")

#define MBARRIER_EXPECT_TX(addr, bytes) \
    asm volatile("mbarrier.arrive.expect_tx.shared.b64 _, [%0], %1;" :: "r"((uint32_t)(addr)), "r"((uint32_t)(bytes)) : "memory")

#define MBARRIER_WAIT_PARITY(mbar_smem_addr, phase_parity) do { \
    uint32_t _mbar = (uint32_t)(mbar_smem_addr); \
    uint32_t _parity = (uint32_t)(phase_parity); \
    uint32_t _done; \
    asm volatile( \
        "{\n\t.reg .pred p;\n\t" \
        "mbarrier.try_wait.parity.acquire.cta.shared::cta.b64 p, [%1], %2;\n\t" \
        "selp.b32 %0, 1, 0, p;\n\t}" \
        : "=r"(_done) : "r"(_mbar), "r"(_parity) : "memory"); \
    if (!_done) { \
        asm volatile( \
            "{\n\t.reg .pred P1;\n\t" \
            "WAIT_LOOP_%=:\n\t" \
            "mbarrier.try_wait.parity.acquire.cta.shared::cta.b64 P1, [%0], %1, 0x989680;\n\t" \
            "@P1 bra.uni WAIT_DONE_%=;\n\t" \
            "bra.uni WAIT_LOOP_%=;\n\t" \
            "WAIT_DONE_%=:\n\t}" \
            :: "r"(_mbar), "r"(_parity) : "memory"); \
    } \
} while(0)

#define MBARRIER_WAIT_PARITY_RELAXED(mbar_smem_addr, phase_parity) do { \
    uint32_t _mbar = (uint32_t)(mbar_smem_addr); \
    uint32_t _parity = (uint32_t)(phase_parity); \
    uint32_t _done; \
    asm volatile( \
        "{\n\t.reg .pred p;\n\t" \
        "mbarrier.try_wait.parity.relaxed.cta.shared::cta.b64 p, [%1], %2, 0x989680;\n\t" \
        "selp.b32 %0, 1, 0, p;\n\t}" \
        : "=r"(_done) : "r"(_mbar), "r"(_parity) : "memory"); \
    if (!_done) { \
        asm volatile( \
            "{\n\t.reg .pred P1;\n\t" \
            "WAIT_LOOP_%=:\n\t" \
            "mbarrier.try_wait.parity.relaxed.cta.shared::cta.b64 P1, [%0], %1, 0x989680;\n\t" \
            "@P1 bra.uni WAIT_DONE_%=;\n\t" \
            "bra.uni WAIT_LOOP_%=;\n\t" \
            "WAIT_DONE_%=:\n\t}" \
            :: "r"(_mbar), "r"(_parity) : "memory"); \
    } \
} while(0)

// tf32 conversion (round-to-nearest) and mma.sync m16n8k8
__device__ __forceinline__ uint32_t f2tf32(float f) {
    uint32_t u;
    asm("cvt.rna.tf32.f32 %0, %1;" : "=r"(u) : "f"(f));
    return u;
}

__device__ __forceinline__ void mma_tf32(float* c, const uint32_t* a, const uint32_t* b) {
    asm volatile(
        "mma.sync.aligned.m16n8k8.row.col.f32.tf32.tf32.f32 "
        "{%0,%1,%2,%3}, {%4,%5,%6,%7}, {%8,%9}, {%0,%1,%2,%3};"
        : "+f"(c[0]), "+f"(c[1]), "+f"(c[2]), "+f"(c[3])
        : "r"(a[0]), "r"(a[1]), "r"(a[2]), "r"(a[3]), "r"(b[0]), "r"(b[1]));
}

// ---------------------------------------------------------------------------
// 1) ada = silu(c) @ ada_w^T + ada_b      [8, 4608]
// ---------------------------------------------------------------------------
__global__ __launch_bounds__(256) void ada_kernel(
    const float* __restrict__ c,
    const float* __restrict__ ada_w,
    const float* __restrict__ ada_b)
{
    __shared__ float sc[CH];
    int b = blockIdx.y;
    for (int k = threadIdx.x; k < CH; k += 256) {
        float v = c[b * CH + k];
        sc[k] = v / (1.f + expf(-v));
    }
    __syncthreads();
    int warp = threadIdx.x >> 5, lane = threadIdx.x & 31;
    int j = blockIdx.x * 8 + warp;
    const float* w = ada_w + (size_t)j * CH;
    float s = 0.f;
    for (int k = lane; k < CH; k += 32) s += sc[k] * w[k];
#pragma unroll
    for (int o = 16; o; o >>= 1) s += __shfl_xor_sync(0xffffffffu, s, o);
    if (lane == 0) g_ada[b * C6 + j] = s + ada_b[j];
}

// ---------------------------------------------------------------------------
// 2) h = LN(x) * (1 + sc[b]) + sh[b]
// ---------------------------------------------------------------------------
__global__ __launch_bounds__(256) void ln_mod_kernel(
    const float* __restrict__ x, int sh_off, int sc_off,
    float* __restrict__ out)
{
    int r = blockIdx.x;
    int b = r >> 10;
    const float* xr = x + (size_t)r * CH;
    int t = threadIdx.x;
    float v[3];
    float s = 0.f, ss = 0.f;
#pragma unroll
    for (int u = 0; u < 3; u++) {
        float w = xr[t + u * 256];
        v[u] = w; s += w; ss += w * w;
    }
#pragma unroll
    for (int o = 16; o; o >>= 1) {
        s  += __shfl_xor_sync(0xffffffffu, s,  o);
        ss += __shfl_xor_sync(0xffffffffu, ss, o);
    }
    __shared__ float rs[8], rss[8];
    __shared__ float smu, srv;
    int warp = t >> 5;
    if ((t & 31) == 0) { rs[warp] = s; rss[warp] = ss; }
    __syncthreads();
    if (t == 0) {
        float ts = 0.f, tss = 0.f;
#pragma unroll
        for (int i = 0; i < 8; i++) { ts += rs[i]; tss += rss[i]; }
        float mu  = ts  * (1.f / (float)CH);
        float var = tss * (1.f / (float)CH) - mu * mu;
        smu = mu;
        srv = rsqrtf(var + 1e-6f);
    }
    __syncthreads();
    float mu = smu, rinv = srv;
    const float* sh  = g_ada + b * C6 + sh_off;
    const float* scm = g_ada + b * C6 + sc_off;
    float* orow = out + (size_t)r * CH;
#pragma unroll
    for (int u = 0; u < 3; u++) {
        int i = t + u * 256;
        orow[i] = (v[u] - mu) * rinv * (1.f + scm[i]) + sh[i];
    }
}

// ---------------------------------------------------------------------------
// 3) TMA + mma.sync tf32 GEMM: C[M,Nc] = A[M,K] @ W[Nc,K]^T + bias (+epi)
//    128x128 tile, K-tile 32 (SW128 swizzled), 4-stage mbarrier pipeline.
//    288 threads: warps 0-7 compute (each 64x32), warp 8 = TMA producer.
//    EPI: 0 = bias; 1 = bias + exact GELU; 2 = resid + gate * (bias+acc)
// ---------------------------------------------------------------------------
#define GSTAGES 4
#define KTILE 32
#define STAGE_BYTES 32768            // A 16KB + B 16KB
#define GEMM_SMEM (1024 + GSTAGES * STAGE_BYTES)

// swizzled byte offset inside a [128 rows x 128B] SW128 tile
__device__ __forceinline__ uint32_t sw_off(int row, int col4) {
    uint32_t off = (uint32_t)(row * 128 + col4 * 4);
    return off ^ ((off >> 3) & 0x70);
}

template <int EPI>
__global__ __launch_bounds__(288, 1) void tc_gemm_kernel(
    const __grid_constant__ CUtensorMap tmA,
    const __grid_constant__ CUtensorMap tmB,
    const float* __restrict__ bias,
    const float* __restrict__ resid,
    const float* __restrict__ gate,
    float* __restrict__ Cout,
    int Nc, int K)
{
    extern __shared__ __align__(1024) char smem[];
    uint32_t sbase = smem_to_u32(smem);
    const int t = threadIdx.x, wid = t >> 5, lane = t & 31;
    const int m0 = blockIdx.y * 128, n0 = blockIdx.x * 128;
    const int KT = K / KTILE;

    const uint32_t mb_full  = sbase + 0;      // GSTAGES x 8B
    const uint32_t mb_empty = sbase + 64;     // GSTAGES x 8B
    char* stg = smem + 1024;

    if (t == 0) {
#pragma unroll
        for (int s = 0; s < GSTAGES; s++) {
            MBARRIER_INIT(mb_full  + 8 * s, 1);
            MBARRIER_INIT(mb_empty + 8 * s, 8);   // 8 compute warps
        }
    }
    __syncthreads();

    if (wid == 8) {
        // -------- TMA producer (lane 0) --------
        if (lane == 0) {
            asm volatile("prefetch.tensormap [%0];" :: "l"(&tmA));
            asm volatile("prefetch.tensormap [%0];" :: "l"(&tmB));
            // prologue: fill all stages
            int npro = KT < GSTAGES ? KT : GSTAGES;
            for (int tt = 0; tt < npro; tt++) {
                uint32_t fm = mb_full + 8 * tt;
                uint32_t aA = smem_to_u32(stg + tt * STAGE_BYTES);
                MBARRIER_EXPECT_TX(fm, STAGE_BYTES);
                int k0 = tt * KTILE;
                asm volatile(
                    "cp.async.bulk.tensor.2d.shared::cta.global.tile.mbarrier::complete_tx::bytes "
                    "[%0], [%1, {%2, %3}], [%4];"
                    :: "r"(aA), "l"(&tmA), "r"(k0), "r"(m0), "r"(fm) : "memory");
                asm volatile(
                    "cp.async.bulk.tensor.2d.shared::cta.global.tile.mbarrier::complete_tx::bytes "
                    "[%0], [%1, {%2, %3}], [%4];"
                    :: "r"(aA + 16384), "l"(&tmB), "r"(k0), "r"(n0), "r"(fm) : "memory");
            }
            // steady state
            int slot = 0, ph = 0;
            for (int tt = GSTAGES; tt < KT; tt++) {
                MBARRIER_WAIT_PARITY_RELAXED(mb_empty + 8 * slot, ph);
                uint32_t fm = mb_full + 8 * slot;
                uint32_t aA = smem_to_u32(stg + slot * STAGE_BYTES);
                MBARRIER_EXPECT_TX(fm, STAGE_BYTES);
                int k0 = tt * KTILE;
                asm volatile(
                    "cp.async.bulk.tensor.2d.shared::cta.global.tile.mbarrier::complete_tx::bytes "
                    "[%0], [%1, {%2, %3}], [%4];"
                    :: "r"(aA), "l"(&tmA), "r"(k0), "r"(m0), "r"(fm) : "memory");
                asm volatile(
                    "cp.async.bulk.tensor.2d.shared::cta.global.tile.mbarrier::complete_tx::bytes "
                    "[%0], [%1, {%2, %3}], [%4];"
                    :: "r"(aA + 16384), "l"(&tmB), "r"(k0), "r"(n0), "r"(fm) : "memory");
                if (++slot == GSTAGES) { slot = 0; ph ^= 1; }
            }
        }
        return;
    }

    // -------- compute warps 0..7: each computes 64(M) x 32(N) --------
    const int wm = wid >> 2;          // 0..1
    const int wn = wid & 3;           // 0..3
    const int g   = lane >> 2;        // groupID 0..7
    const int ctg = lane & 3;         // threadID_in_group 0..3

    float acc[4][4][4];
#pragma unroll
    for (int im = 0; im < 4; im++)
#pragma unroll
        for (int in = 0; in < 4; in++)
#pragma unroll
            for (int r = 0; r < 4; r++) acc[im][in][r] = 0.f;

    int slot = 0, ph = 0;
    for (int tt = 0; tt < KT; tt++) {
        MBARRIER_WAIT_PARITY(mb_full + 8 * slot, ph);
        const char* At = stg + slot * STAGE_BYTES;
        const char* Bt = At + 16384;

#pragma unroll
        for (int kk = 0; kk < 4; kk++) {
            const int kc = kk * 8;
            uint32_t afr[4][4];
#pragma unroll
            for (int im = 0; im < 4; im++) {
                int r0 = wm * 64 + im * 16;
                afr[im][0] = f2tf32(*(const float*)(At + sw_off(r0 + g,     kc + ctg)));
                afr[im][1] = f2tf32(*(const float*)(At + sw_off(r0 + g + 8, kc + ctg)));
                afr[im][2] = f2tf32(*(const float*)(At + sw_off(r0 + g,     kc + ctg + 4)));
                afr[im][3] = f2tf32(*(const float*)(At + sw_off(r0 + g + 8, kc + ctg + 4)));
            }
            uint32_t bfr[4][2];
#pragma unroll
            for (int in = 0; in < 4; in++) {
                int nr = wn * 32 + in * 8 + g;
                bfr[in][0] = f2tf32(*(const float*)(Bt + sw_off(nr, kc + ctg)));
                bfr[in][1] = f2tf32(*(const float*)(Bt + sw_off(nr, kc + ctg + 4)));
            }
#pragma unroll
            for (int im = 0; im < 4; im++)
#pragma unroll
                for (int in = 0; in < 4; in++)
                    mma_tf32(acc[im][in], afr[im], bfr[in]);
        }

        if (lane == 0) MBARRIER_ARRIVE(mb_empty + 8 * slot);
        if (++slot == GSTAGES) { slot = 0; ph ^= 1; }
    }

    // -------- epilogue --------
    const int bidx = m0 >> 10;        // batch (tile never straddles: 1024%128==0)
    const int mB = m0 + wm * 64;
    const int nB = n0 + wn * 32;
#pragma unroll
    for (int im = 0; im < 4; im++) {
        int r = mB + im * 16 + g;
#pragma unroll
        for (int in = 0; in < 4; in++) {
            int n = nB + in * 8 + 2 * ctg;
            float b0 = bias[n], b1 = bias[n + 1];
#pragma unroll
            for (int half = 0; half < 2; half++) {
                int m = r + half * 8;
                float v0 = acc[im][in][2 * half + 0] + b0;
                float v1 = acc[im][in][2 * half + 1] + b1;
                if (EPI == 1) {
                    v0 = 0.5f * v0 * (1.f + erff(v0 * 0.70710678118654752f));
                    v1 = 0.5f * v1 * (1.f + erff(v1 * 0.70710678118654752f));
                }
                if (EPI == 2) {
                    const float2 rr = *(const float2*)&resid[(size_t)m * Nc + n];
                    float g0 = gate[bidx * C6 + n], g1 = gate[bidx * C6 + n + 1];
                    v0 = rr.x + g0 * v0;
                    v1 = rr.y + g1 * v1;
                }
                *(float2*)&Cout[(size_t)m * Nc + n] = make_float2(v0, v1);
            }
        }
    }
}

// ---------------------------------------------------------------------------
// 4) Attention (fp32 flash-style, unchanged)
// ---------------------------------------------------------------------------
__global__ __launch_bounds__(256) void attn_kernel(
    const float* __restrict__ qkv, float* __restrict__ out)
{
    __shared__ float Qs[64 * 64];
    __shared__ float KP[64 * 64];
    __shared__ float Vs[64 * 64];

    int b = blockIdx.z, h = blockIdx.y;
    int q0 = blockIdx.x * 64;
    int t = threadIdx.x;
    int ty = t >> 4, tx = t & 15;

    const float* base  = qkv + (size_t)(b * SEQ) * C3 + h * HDIM;
    const float* kbase = base + CH;
    const float* vbase = base + 2 * CH;

#pragma unroll
    for (int u = 0; u < 4; u++) {
        int idx = t + u * 256;
        int r   = idx >> 4;
        int d4  = (idx & 15) << 2;
        *(float4*)&Qs[r * 64 + d4] =
            *(const float4*)(base + (size_t)(q0 + r) * C3 + d4);
    }

    float m_i[4], l_i[4], acc[4][4];
#pragma unroll
    for (int i = 0; i < 4; i++) {
        m_i[i] = -1e30f; l_i[i] = 0.f;
#pragma unroll
        for (int j = 0; j < 4; j++) acc[i][j] = 0.f;
    }

    for (int kt = 0; kt < 16; kt++) {
        int kr0 = kt * 64;
#pragma unroll
        for (int u = 0; u < 4; u++) {
            int idx = t + u * 256;
            int r   = idx >> 4;
            int d4  = (idx & 15) << 2;
            float4 kv = *(const float4*)(kbase + (size_t)(kr0 + r) * C3 + d4);
            KP[(d4 + 0) * 64 + r] = kv.x;
            KP[(d4 + 1) * 64 + r] = kv.y;
            KP[(d4 + 2) * 64 + r] = kv.z;
            KP[(d4 + 3) * 64 + r] = kv.w;
            *(float4*)&Vs[r * 64 + d4] =
                *(const float4*)(vbase + (size_t)(kr0 + r) * C3 + d4);
        }
        __syncthreads();

        float s[4][4];
#pragma unroll
        for (int i = 0; i < 4; i++)
#pragma unroll
            for (int j = 0; j < 4; j++) s[i][j] = 0.f;

        for (int d = 0; d < 64; d += 4) {
            float4 q4[4];
#pragma unroll
            for (int i = 0; i < 4; i++)
                q4[i] = *(const float4*)&Qs[(ty * 4 + i) * 64 + d];
#pragma unroll
            for (int dd = 0; dd < 4; dd++) {
                float4 kf = *(const float4*)&KP[(d + dd) * 64 + tx * 4];
#pragma unroll
                for (int i = 0; i < 4; i++) {
                    float qv = ((const float*)&q4[i])[dd];
                    s[i][0] = fmaf(qv, kf.x, s[i][0]);
                    s[i][1] = fmaf(qv, kf.y, s[i][1]);
                    s[i][2] = fmaf(qv, kf.z, s[i][2]);
                    s[i][3] = fmaf(qv, kf.w, s[i][3]);
                }
            }
        }
#pragma unroll
        for (int i = 0; i < 4; i++)
#pragma unroll
            for (int j = 0; j < 4; j++) s[i][j] *= 0.125f;

        float p[4][4], alpha[4];
#pragma unroll
        for (int i = 0; i < 4; i++) {
            float rmax = fmaxf(fmaxf(s[i][0], s[i][1]), fmaxf(s[i][2], s[i][3]));
#pragma unroll
            for (int o = 1; o < 16; o <<= 1)
                rmax = fmaxf(rmax, __shfl_xor_sync(0xffffffffu, rmax, o));
            float mnew = fmaxf(m_i[i], rmax);
            alpha[i] = __expf(m_i[i] - mnew);
            float rsum = 0.f;
#pragma unroll
            for (int j = 0; j < 4; j++) {
                p[i][j] = __expf(s[i][j] - mnew);
                rsum += p[i][j];
            }
#pragma unroll
            for (int o = 1; o < 16; o <<= 1)
                rsum += __shfl_xor_sync(0xffffffffu, rsum, o);
            l_i[i] = l_i[i] * alpha[i] + rsum;
            m_i[i] = mnew;
#pragma unroll
            for (int j = 0; j < 4; j++) acc[i][j] *= alpha[i];
        }
        __syncthreads();

#pragma unroll
        for (int i = 0; i < 4; i++)
            *(float4*)&KP[(ty * 4 + i) * 64 + tx * 4] =
                make_float4(p[i][0], p[i][1], p[i][2], p[i][3]);
        __syncthreads();

        for (int kk = 0; kk < 64; kk += 4) {
            float4 p4[4];
#pragma unroll
            for (int i = 0; i < 4; i++)
                p4[i] = *(const float4*)&KP[(ty * 4 + i) * 64 + kk];
#pragma unroll
            for (int dd = 0; dd < 4; dd++) {
                float4 vf = *(const float4*)&Vs[(kk + dd) * 64 + tx * 4];
#pragma unroll
                for (int i = 0; i < 4; i++) {
                    float pv = ((const float*)&p4[i])[dd];
                    acc[i][0] = fmaf(pv, vf.x, acc[i][0]);
                    acc[i][1] = fmaf(pv, vf.y, acc[i][1]);
                    acc[i][2] = fmaf(pv, vf.z, acc[i][2]);
                    acc[i][3] = fmaf(pv, vf.w, acc[i][3]);
                }
            }
        }
        __syncthreads();
    }

#pragma unroll
    for (int i = 0; i < 4; i++) {
        float inv = 1.f / l_i[i];
        float4 o = make_float4(acc[i][0] * inv, acc[i][1] * inv,
                               acc[i][2] * inv, acc[i][3] * inv);
        *(float4*)&out[(size_t)(b * SEQ + q0 + ty * 4 + i) * CH + h * HDIM + tx * 4] = o;
    }
}

// ---------------------------------------------------------------------------
// Host: tensormap construction (driver entry point fetched at runtime)
// ---------------------------------------------------------------------------
typedef CUresult (*PFN_tmEncode)(
    CUtensorMap*, CUtensorMapDataType, cuuint32_t, void*,
    const cuuint64_t*, const cuuint64_t*, const cuuint32_t*, const cuuint32_t*,
    CUtensorMapInterleave, CUtensorMapSwizzle, CUtensorMapL2promotion,
    CUtensorMapFloatOOBfill);

static PFN_tmEncode get_tm_encode() {
    void* fn = nullptr;
#if CUDART_VERSION >= 12050
    cudaDriverEntryPointQueryResult qr;
    cudaGetDriverEntryPointByVersion("cuTensorMapEncodeTiled", &fn, 12000,
                                     cudaEnableDefault, &qr);
#else
    cudaDriverEntryPointQueryResult qr;
    cudaGetDriverEntryPoint("cuTensorMapEncodeTiled", &fn, cudaEnableDefault, &qr);
#endif
    return (PFN_tmEncode)fn;
}

static void make_tm(PFN_tmEncode enc, CUtensorMap* tm, const void* p, int K, int M) {
    cuuint64_t dims[2]    = {(cuuint64_t)K, (cuuint64_t)M};
    cuuint64_t strides[1] = {(cuuint64_t)K * 4};
    cuuint32_t box[2]     = {32u, 128u};
    cuuint32_t es[2]      = {1u, 1u};
    enc(tm, CU_TENSOR_MAP_DATA_TYPE_FLOAT32, 2, (void*)p, dims, strides, box, es,
        CU_TENSOR_MAP_INTERLEAVE_NONE, CU_TENSOR_MAP_SWIZZLE_128B,
        CU_TENSOR_MAP_L2_PROMOTION_L2_128B, CU_TENSOR_MAP_FLOAT_OOB_FILL_NONE);
}

// ---------------------------------------------------------------------------
// Launch
// ---------------------------------------------------------------------------
extern "C" void kernel_launch(void* const* d_in, const int* in_sizes, int n_in,
                              void* d_out, int out_size)
{
    const float* x      = (const float*)d_in[0];
    const float* c      = (const float*)d_in[1];
    const float* qkv_w  = (const float*)d_in[2];
    const float* qkv_b  = (const float*)d_in[3];
    const float* proj_w = (const float*)d_in[4];
    const float* proj_b = (const float*)d_in[5];
    const float* fc1_w  = (const float*)d_in[6];
    const float* fc1_b  = (const float*)d_in[7];
    const float* fc2_w  = (const float*)d_in[8];
    const float* fc2_b  = (const float*)d_in[9];
    const float* ada_w  = (const float*)d_in[10];
    const float* ada_b  = (const float*)d_in[11];
    float* out = (float*)d_out;

    float *p_ada, *p_h, *p_qkv, *p_att, *p_x1, *p_mlp;
    cudaGetSymbolAddress((void**)&p_ada, g_ada);
    cudaGetSymbolAddress((void**)&p_h,   g_h);
    cudaGetSymbolAddress((void**)&p_qkv, g_qkv);
    cudaGetSymbolAddress((void**)&p_att, g_att);
    cudaGetSymbolAddress((void**)&p_x1,  g_x1);
    cudaGetSymbolAddress((void**)&p_mlp, g_mlp);

    PFN_tmEncode enc = get_tm_encode();
    alignas(64) CUtensorMap tm_h, tm_att, tm_mlp, tm_qkvw, tm_projw, tm_fc1w, tm_fc2w;
    make_tm(enc, &tm_h,     p_h,    CH,    ROWS);
    make_tm(enc, &tm_att,   p_att,  CH,    ROWS);
    make_tm(enc, &tm_mlp,   p_mlp,  HFDIM, ROWS);
    make_tm(enc, &tm_qkvw,  qkv_w,  CH,    C3);
    make_tm(enc, &tm_projw, proj_w, CH,    CH);
    make_tm(enc, &tm_fc1w,  fc1_w,  CH,    HFDIM);
    make_tm(enc, &tm_fc2w,  fc2_w,  HFDIM, CH);

    cudaFuncSetAttribute(tc_gemm_kernel<0>, cudaFuncAttributeMaxDynamicSharedMemorySize, GEMM_SMEM);
    cudaFuncSetAttribute(tc_gemm_kernel<1>, cudaFuncAttributeMaxDynamicSharedMemorySize, GEMM_SMEM);
    cudaFuncSetAttribute(tc_gemm_kernel<2>, cudaFuncAttributeMaxDynamicSharedMemorySize, GEMM_SMEM);

    // 1) adaLN parameters
    ada_kernel<<<dim3(C6 / 8, BATCH), 256>>>(c, ada_w, ada_b);

    // 2) h = modulate(LN(x), sh_msa, sc_msa)
    ln_mod_kernel<<<ROWS, 256>>>(x, 0, 768, p_h);

    // 3) qkv = h @ qkv_w^T + qkv_b
    tc_gemm_kernel<0><<<dim3(C3 / 128, ROWS / 128), 288, GEMM_SMEM>>>(
        tm_h, tm_qkvw, qkv_b, nullptr, nullptr, p_qkv, C3, CH);

    // 4) attention -> g_att
    attn_kernel<<<dim3(SEQ / 64, NHEAD, BATCH), 256>>>(p_qkv, p_att);

    // 5) x1 = x + g_msa * (attn @ proj_w^T + proj_b)
    tc_gemm_kernel<2><<<dim3(CH / 128, ROWS / 128), 288, GEMM_SMEM>>>(
        tm_att, tm_projw, proj_b, x, p_ada + 1536, p_x1, CH, CH);

    // 6) h = modulate(LN(x1), sh_mlp, sc_mlp)
    ln_mod_kernel<<<ROWS, 256>>>(p_x1, 2304, 3072, p_h);

    // 7) mlp_hidden = gelu(h @ fc1_w^T + fc1_b)
    tc_gemm_kernel<1><<<dim3(HFDIM / 128, ROWS / 128), 288, GEMM_SMEM>>>(
        tm_h, tm_fc1w, fc1_b, nullptr, nullptr, p_mlp, HFDIM, CH);

    // 8) out = x1 + g_mlp * (mlp_hidden @ fc2_w^T + fc2_b)
    tc_gemm_kernel<2><<<dim3(CH / 128, ROWS / 128), 288, GEMM_SMEM>>>(
        tm_mlp, tm_fc2w, fc2_b, p_x1, p_ada + 3840, out, CH, HFDIM);
}

// round 4
// speedup vs baseline: 3.1830x; 1.4923x over previous
#include <cuda_runtime.h>
#include <cuda.h>
#include <math.h>
#include <stdint.h>

// Problem constants
#define BATCH 8
#define SEQ   1024
#define CH    768
#define C3    2304      // 3*CH
#define C6    4608      // 6*CH
#define HFDIM 3072      // 4*CH
#define NHEAD 12
#define HDIM  64
#define ROWS  8192      // BATCH*SEQ

// ---------------------------------------------------------------------------
// Scratch (device globals — no allocation allowed)
// ---------------------------------------------------------------------------
__device__ float g_ada[BATCH * C6];
__device__ float g_h  [(size_t)ROWS * CH];
__device__ float g_qkv[(size_t)ROWS * C3];
__device__ float g_att[(size_t)ROWS * CH];
__device__ float g_x1 [(size_t)ROWS * CH];
__device__ float g_mlp[(size_t)ROWS * HFDIM];

// ---------------------------------------------------------------------------
// PTX helpers (sm_90-base ISA only: mbarrier + TMA + cp.async + mma.sync)
// ---------------------------------------------------------------------------
__device__ __forceinline__ uint32_t smem_to_u32(const void* p) {
    uint32_t a;
    asm("{ .reg .u64 t; cvta.to.shared.u64 t, %1; cvt.u32.u64 %0, t; }"
        : "=r"(a) : "l"(p));
    return a;
}

#define MBARRIER_INIT(addr, cnt) \
    asm volatile("mbarrier.init.shared.b64 [%0], %1;" :: "r"((uint32_t)(addr)), "r"((uint32_t)(cnt)) : "memory")

#define MBARRIER_ARRIVE(addr) \
    asm volatile("mbarrier.arrive.shared.b64 _, [%0];" :: "r"((uint32_t)(addr)) : "memory")

#define MBARRIER_EXPECT_TX(addr, bytes) \
    asm volatile("mbarrier.arrive.expect_tx.shared.b64 _, [%0], %1;" :: "r"((uint32_t)(addr)), "r"((uint32_t)(bytes)) : "memory")

#define MBARRIER_WAIT_PARITY(mbar_smem_addr, phase_parity) do { \
    uint32_t _mbar = (uint32_t)(mbar_smem_addr); \
    uint32_t _parity = (uint32_t)(phase_parity); \
    uint32_t _done; \
    asm volatile( \
        "{\n\t.reg .pred p;\n\t" \
        "mbarrier.try_wait.parity.acquire.cta.shared::cta.b64 p, [%1], %2;\n\t" \
        "selp.b32 %0, 1, 0, p;\n\t}" \
        : "=r"(_done) : "r"(_mbar), "r"(_parity) : "memory"); \
    if (!_done) { \
        asm volatile( \
            "{\n\t.reg .pred P1;\n\t" \
            "WAIT_LOOP_%=:\n\t" \
            "mbarrier.try_wait.parity.acquire.cta.shared::cta.b64 P1, [%0], %1, 0x989680;\n\t" \
            "@P1 bra.uni WAIT_DONE_%=;\n\t" \
            "bra.uni WAIT_LOOP_%=;\n\t" \
            "WAIT_DONE_%=:\n\t}" \
            :: "r"(_mbar), "r"(_parity) : "memory"); \
    } \
} while(0)

#define MBARRIER_WAIT_PARITY_RELAXED(mbar_smem_addr, phase_parity) do { \
    uint32_t _mbar = (uint32_t)(mbar_smem_addr); \
    uint32_t _parity = (uint32_t)(phase_parity); \
    uint32_t _done; \
    asm volatile( \
        "{\n\t.reg .pred p;\n\t" \
        "mbarrier.try_wait.parity.relaxed.cta.shared::cta.b64 p, [%1], %2, 0x989680;\n\t" \
        "selp.b32 %0, 1, 0, p;\n\t}" \
        : "=r"(_done) : "r"(_mbar), "r"(_parity) : "memory"); \
    if (!_done) { \
        asm volatile( \
            "{\n\t.reg .pred P1;\n\t" \
            "WAIT_LOOP_%=:\n\t" \
            "mbarrier.try_wait.parity.relaxed.cta.shared::cta.b64 P1, [%0], %1, 0x989680;\n\t" \
            "@P1 bra.uni WAIT_DONE_%=;\n\t" \
            "bra.uni WAIT_LOOP_%=;\n\t" \
            "WAIT_DONE_%=:\n\t}" \
            :: "r"(_mbar), "r"(_parity) : "memory"); \
    } \
} while(0)

__device__ __forceinline__ uint32_t f2tf32(float f) {
    uint32_t u;
    asm("cvt.rna.tf32.f32 %0, %1;" : "=r"(u) : "f"(f));
    return u;
}

__device__ __forceinline__ void mma_tf32(float* c, const uint32_t* a, const uint32_t* b) {
    asm volatile(
        "mma.sync.aligned.m16n8k8.row.col.f32.tf32.tf32.f32 "
        "{%0,%1,%2,%3}, {%4,%5,%6,%7}, {%8,%9}, {%0,%1,%2,%3};"
        : "+f"(c[0]), "+f"(c[1]), "+f"(c[2]), "+f"(c[3])
        : "r"(a[0]), "r"(a[1]), "r"(a[2]), "r"(a[3]), "r"(b[0]), "r"(b[1]));
}

__device__ __forceinline__ void cpasync16(uint32_t dst, const void* src) {
    asm volatile("cp.async.cg.shared.global [%0], [%1], 16;" :: "r"(dst), "l"(src) : "memory");
}
#define CPASYNC_COMMIT() asm volatile("cp.async.commit_group;" ::: "memory")
#define CPASYNC_WAIT0()  asm volatile("cp.async.wait_group 0;" ::: "memory")

// ---------------------------------------------------------------------------
// 1) ada = silu(c) @ ada_w^T + ada_b      [8, 4608]
// ---------------------------------------------------------------------------
__global__ __launch_bounds__(256) void ada_kernel(
    const float* __restrict__ c,
    const float* __restrict__ ada_w,
    const float* __restrict__ ada_b)
{
    __shared__ float sc[CH];
    int b = blockIdx.y;
    for (int k = threadIdx.x; k < CH; k += 256) {
        float v = c[b * CH + k];
        sc[k] = v / (1.f + expf(-v));
    }
    __syncthreads();
    int warp = threadIdx.x >> 5, lane = threadIdx.x & 31;
    int j = blockIdx.x * 8 + warp;
    const float* w = ada_w + (size_t)j * CH;
    float s = 0.f;
    for (int k = lane; k < CH; k += 32) s += sc[k] * w[k];
#pragma unroll
    for (int o = 16; o; o >>= 1) s += __shfl_xor_sync(0xffffffffu, s, o);
    if (lane == 0) g_ada[b * C6 + j] = s + ada_b[j];
}

// ---------------------------------------------------------------------------
// 2) h = LN(x) * (1 + sc[b]) + sh[b]
// ---------------------------------------------------------------------------
__global__ __launch_bounds__(256) void ln_mod_kernel(
    const float* __restrict__ x, int sh_off, int sc_off,
    float* __restrict__ out)
{
    int r = blockIdx.x;
    int b = r >> 10;
    const float* xr = x + (size_t)r * CH;
    int t = threadIdx.x;
    float v[3];
    float s = 0.f, ss = 0.f;
#pragma unroll
    for (int u = 0; u < 3; u++) {
        float w = xr[t + u * 256];
        v[u] = w; s += w; ss += w * w;
    }
#pragma unroll
    for (int o = 16; o; o >>= 1) {
        s  += __shfl_xor_sync(0xffffffffu, s,  o);
        ss += __shfl_xor_sync(0xffffffffu, ss, o);
    }
    __shared__ float rs[8], rss[8];
    __shared__ float smu, srv;
    int warp = t >> 5;
    if ((t & 31) == 0) { rs[warp] = s; rss[warp] = ss; }
    __syncthreads();
    if (t == 0) {
        float ts = 0.f, tss = 0.f;
#pragma unroll
        for (int i = 0; i < 8; i++) { ts += rs[i]; tss += rss[i]; }
        float mu  = ts  * (1.f / (float)CH);
        float var = tss * (1.f / (float)CH) - mu * mu;
        smu = mu;
        srv = rsqrtf(var + 1e-6f);
    }
    __syncthreads();
    float mu = smu, rinv = srv;
    const float* sh  = g_ada + b * C6 + sh_off;
    const float* scm = g_ada + b * C6 + sc_off;
    float* orow = out + (size_t)r * CH;
#pragma unroll
    for (int u = 0; u < 3; u++) {
        int i = t + u * 256;
        orow[i] = (v[u] - mu) * rinv * (1.f + scm[i]) + sh[i];
    }
}

// ---------------------------------------------------------------------------
// 3) TMA + mma.sync tf32 GEMM (unchanged from round 3)
// ---------------------------------------------------------------------------
#define GSTAGES 4
#define KTILE 32
#define STAGE_BYTES 32768
#define GEMM_SMEM (1024 + GSTAGES * STAGE_BYTES)

__device__ __forceinline__ uint32_t sw_off(int row, int col4) {
    uint32_t off = (uint32_t)(row * 128 + col4 * 4);
    return off ^ ((off >> 3) & 0x70);
}

template <int EPI>
__global__ __launch_bounds__(288, 1) void tc_gemm_kernel(
    const __grid_constant__ CUtensorMap tmA,
    const __grid_constant__ CUtensorMap tmB,
    const float* __restrict__ bias,
    const float* __restrict__ resid,
    const float* __restrict__ gate,
    float* __restrict__ Cout,
    int Nc, int K)
{
    extern __shared__ __align__(1024) char smem[];
    uint32_t sbase = smem_to_u32(smem);
    const int t = threadIdx.x, wid = t >> 5, lane = t & 31;
    const int m0 = blockIdx.y * 128, n0 = blockIdx.x * 128;
    const int KT = K / KTILE;

    const uint32_t mb_full  = sbase + 0;
    const uint32_t mb_empty = sbase + 64;
    char* stg = smem + 1024;

    if (t == 0) {
#pragma unroll
        for (int s = 0; s < GSTAGES; s++) {
            MBARRIER_INIT(mb_full  + 8 * s, 1);
            MBARRIER_INIT(mb_empty + 8 * s, 8);
        }
    }
    __syncthreads();

    if (wid == 8) {
        if (lane == 0) {
            asm volatile("prefetch.tensormap [%0];" :: "l"(&tmA));
            asm volatile("prefetch.tensormap [%0];" :: "l"(&tmB));
            int npro = KT < GSTAGES ? KT : GSTAGES;
            for (int tt = 0; tt < npro; tt++) {
                uint32_t fm = mb_full + 8 * tt;
                uint32_t aA = smem_to_u32(stg + tt * STAGE_BYTES);
                MBARRIER_EXPECT_TX(fm, STAGE_BYTES);
                int k0 = tt * KTILE;
                asm volatile(
                    "cp.async.bulk.tensor.2d.shared::cta.global.tile.mbarrier::complete_tx::bytes "
                    "[%0], [%1, {%2, %3}], [%4];"
                    :: "r"(aA), "l"(&tmA), "r"(k0), "r"(m0), "r"(fm) : "memory");
                asm volatile(
                    "cp.async.bulk.tensor.2d.shared::cta.global.tile.mbarrier::complete_tx::bytes "
                    "[%0], [%1, {%2, %3}], [%4];"
                    :: "r"(aA + 16384), "l"(&tmB), "r"(k0), "r"(n0), "r"(fm) : "memory");
            }
            int slot = 0, ph = 0;
            for (int tt = GSTAGES; tt < KT; tt++) {
                MBARRIER_WAIT_PARITY_RELAXED(mb_empty + 8 * slot, ph);
                uint32_t fm = mb_full + 8 * slot;
                uint32_t aA = smem_to_u32(stg + slot * STAGE_BYTES);
                MBARRIER_EXPECT_TX(fm, STAGE_BYTES);
                int k0 = tt * KTILE;
                asm volatile(
                    "cp.async.bulk.tensor.2d.shared::cta.global.tile.mbarrier::complete_tx::bytes "
                    "[%0], [%1, {%2, %3}], [%4];"
                    :: "r"(aA), "l"(&tmA), "r"(k0), "r"(m0), "r"(fm) : "memory");
                asm volatile(
                    "cp.async.bulk.tensor.2d.shared::cta.global.tile.mbarrier::complete_tx::bytes "
                    "[%0], [%1, {%2, %3}], [%4];"
                    :: "r"(aA + 16384), "l"(&tmB), "r"(k0), "r"(n0), "r"(fm) : "memory");
                if (++slot == GSTAGES) { slot = 0; ph ^= 1; }
            }
        }
        return;
    }

    const int wm = wid >> 2;
    const int wn = wid & 3;
    const int g   = lane >> 2;
    const int ctg = lane & 3;

    float acc[4][4][4];
#pragma unroll
    for (int im = 0; im < 4; im++)
#pragma unroll
        for (int in = 0; in < 4; in++)
#pragma unroll
            for (int r = 0; r < 4; r++) acc[im][in][r] = 0.f;

    int slot = 0, ph = 0;
    for (int tt = 0; tt < KT; tt++) {
        MBARRIER_WAIT_PARITY(mb_full + 8 * slot, ph);
        const char* At = stg + slot * STAGE_BYTES;
        const char* Bt = At + 16384;

#pragma unroll
        for (int kk = 0; kk < 4; kk++) {
            const int kc = kk * 8;
            uint32_t afr[4][4];
#pragma unroll
            for (int im = 0; im < 4; im++) {
                int r0 = wm * 64 + im * 16;
                afr[im][0] = f2tf32(*(const float*)(At + sw_off(r0 + g,     kc + ctg)));
                afr[im][1] = f2tf32(*(const float*)(At + sw_off(r0 + g + 8, kc + ctg)));
                afr[im][2] = f2tf32(*(const float*)(At + sw_off(r0 + g,     kc + ctg + 4)));
                afr[im][3] = f2tf32(*(const float*)(At + sw_off(r0 + g + 8, kc + ctg + 4)));
            }
            uint32_t bfr[4][2];
#pragma unroll
            for (int in = 0; in < 4; in++) {
                int nr = wn * 32 + in * 8 + g;
                bfr[in][0] = f2tf32(*(const float*)(Bt + sw_off(nr, kc + ctg)));
                bfr[in][1] = f2tf32(*(const float*)(Bt + sw_off(nr, kc + ctg + 4)));
            }
#pragma unroll
            for (int im = 0; im < 4; im++)
#pragma unroll
                for (int in = 0; in < 4; in++)
                    mma_tf32(acc[im][in], afr[im], bfr[in]);
        }

        if (lane == 0) MBARRIER_ARRIVE(mb_empty + 8 * slot);
        if (++slot == GSTAGES) { slot = 0; ph ^= 1; }
    }

    const int bidx = m0 >> 10;
    const int mB = m0 + wm * 64;
    const int nB = n0 + wn * 32;
#pragma unroll
    for (int im = 0; im < 4; im++) {
        int r = mB + im * 16 + g;
#pragma unroll
        for (int in = 0; in < 4; in++) {
            int n = nB + in * 8 + 2 * ctg;
            float b0 = bias[n], b1 = bias[n + 1];
#pragma unroll
            for (int half = 0; half < 2; half++) {
                int m = r + half * 8;
                float v0 = acc[im][in][2 * half + 0] + b0;
                float v1 = acc[im][in][2 * half + 1] + b1;
                if (EPI == 1) {
                    v0 = 0.5f * v0 * (1.f + erff(v0 * 0.70710678118654752f));
                    v1 = 0.5f * v1 * (1.f + erff(v1 * 0.70710678118654752f));
                }
                if (EPI == 2) {
                    const float2 rr = *(const float2*)&resid[(size_t)m * Nc + n];
                    float g0 = gate[bidx * C6 + n], g1 = gate[bidx * C6 + n + 1];
                    v0 = rr.x + g0 * v0;
                    v1 = rr.y + g1 * v1;
                }
                *(float2*)&Cout[(size_t)m * Nc + n] = make_float2(v0, v1);
            }
        }
    }
}

// ---------------------------------------------------------------------------
// 4) Attention with mma.sync tf32 (flash-style).
//    CTA = 4 warps, 64 q-rows (16/warp). K/V tiles of 64 double-buffered via
//    cp.async. Smem rows padded to 68 floats for conflict-free frag loads.
// ---------------------------------------------------------------------------
#define AT_W 68
#define AT_TILE_F (64 * AT_W)
// floats: Q 1 tile, K 2 bufs, V 2 bufs, P 4 warps x 16 rows
#define ATT_SMEM ((AT_TILE_F * 5 + 4 * 16 * AT_W) * 4)

__global__ __launch_bounds__(128, 2) void attn_tc_kernel(
    const float* __restrict__ qkv, float* __restrict__ out)
{
    extern __shared__ __align__(16) float as[];
    float* Qs = as;                       // [64][68]
    float* Ks = Qs + AT_TILE_F;           // 2 x [64][68]
    float* Vs = Ks + 2 * AT_TILE_F;       // 2 x [64][68]
    float* Ps = Vs + 2 * AT_TILE_F;       // 4 x [16][68]

    const int b = blockIdx.z, h = blockIdx.y;
    const int q0 = blockIdx.x * 64;
    const int t = threadIdx.x, wq = t >> 5, lane = t & 31;
    const int g = lane >> 2, ctg = lane & 3;

    const float* qb = qkv + (size_t)(b * SEQ) * C3 + h * HDIM;
    const float* kb = qb + CH;
    const float* vb = qb + 2 * CH;

    // issue K/V tile 0 loads first (cp.async)
    {
        uint32_t kd = smem_to_u32(Ks);
        uint32_t vd = smem_to_u32(Vs);
#pragma unroll
        for (int u = 0; u < 8; u++) {
            int i = t + u * 128;               // 1024 16B-chunks per tile
            int r = i >> 4, d4 = (i & 15) << 2;
            uint32_t so = (uint32_t)(r * AT_W + d4) * 4;
            cpasync16(kd + so, kb + (size_t)r * C3 + d4);
            cpasync16(vd + so, vb + (size_t)r * C3 + d4);
        }
        CPASYNC_COMMIT();
    }

    // load Q tile (scaled by 1/8)
#pragma unroll
    for (int u = 0; u < 8; u++) {
        int i = t + u * 128;
        int r = i >> 4, d4 = (i & 15) << 2;
        float4 v = *(const float4*)(qb + (size_t)(q0 + r) * C3 + d4);
        *(float4*)&Qs[r * AT_W + d4] =
            make_float4(v.x * 0.125f, v.y * 0.125f, v.z * 0.125f, v.w * 0.125f);
    }
    __syncthreads();

    // preload Q fragments (rna-rounded once)
    uint32_t qf[8][4];
    {
        const float* Qw = Qs + (wq * 16) * AT_W;
#pragma unroll
        for (int kk = 0; kk < 8; kk++) {
            int kc = kk * 8;
            qf[kk][0] = f2tf32(Qw[g * AT_W + kc + ctg]);
            qf[kk][1] = f2tf32(Qw[(g + 8) * AT_W + kc + ctg]);
            qf[kk][2] = f2tf32(Qw[g * AT_W + kc + ctg + 4]);
            qf[kk][3] = f2tf32(Qw[(g + 8) * AT_W + kc + ctg + 4]);
        }
    }

    float m0 = -1e30f, m1 = -1e30f, l0 = 0.f, l1 = 0.f;
    float oac[8][4];
#pragma unroll
    for (int in = 0; in < 8; in++)
#pragma unroll
        for (int r = 0; r < 4; r++) oac[in][r] = 0.f;

    float* Pw = Ps + wq * 16 * AT_W;

    for (int kt = 0; kt < 16; kt++) {
        CPASYNC_WAIT0();
        __syncthreads();
        // prefetch next tile
        if (kt + 1 < 16) {
            int nb = (kt + 1) & 1;
            int kr0 = (kt + 1) * 64;
            uint32_t kd = smem_to_u32(Ks + nb * AT_TILE_F);
            uint32_t vd = smem_to_u32(Vs + nb * AT_TILE_F);
#pragma unroll
            for (int u = 0; u < 8; u++) {
                int i = t + u * 128;
                int r = i >> 4, d4 = (i & 15) << 2;
                uint32_t so = (uint32_t)(r * AT_W + d4) * 4;
                cpasync16(kd + so, kb + (size_t)(kr0 + r) * C3 + d4);
                cpasync16(vd + so, vb + (size_t)(kr0 + r) * C3 + d4);
            }
            CPASYNC_COMMIT();
        }

        const float* Kt = Ks + (kt & 1) * AT_TILE_F;
        const float* Vt = Vs + (kt & 1) * AT_TILE_F;

        // S = Q @ K^T
        float sac[8][4];
#pragma unroll
        for (int in = 0; in < 8; in++)
#pragma unroll
            for (int r = 0; r < 4; r++) sac[in][r] = 0.f;

#pragma unroll
        for (int kk = 0; kk < 8; kk++) {
            int kc = kk * 8;
            uint32_t bfr[8][2];
#pragma unroll
            for (int in = 0; in < 8; in++) {
                int nr = in * 8 + g;
                bfr[in][0] = __float_as_uint(Kt[nr * AT_W + kc + ctg]);
                bfr[in][1] = __float_as_uint(Kt[nr * AT_W + kc + ctg + 4]);
            }
#pragma unroll
            for (int in = 0; in < 8; in++)
                mma_tf32(sac[in], qf[kk], bfr[in]);
        }

        // online softmax (rows g and g+8)
        float mx0 = -1e30f, mx1 = -1e30f;
#pragma unroll
        for (int in = 0; in < 8; in++) {
            mx0 = fmaxf(mx0, fmaxf(sac[in][0], sac[in][1]));
            mx1 = fmaxf(mx1, fmaxf(sac[in][2], sac[in][3]));
        }
        mx0 = fmaxf(mx0, __shfl_xor_sync(0xffffffffu, mx0, 1));
        mx0 = fmaxf(mx0, __shfl_xor_sync(0xffffffffu, mx0, 2));
        mx1 = fmaxf(mx1, __shfl_xor_sync(0xffffffffu, mx1, 1));
        mx1 = fmaxf(mx1, __shfl_xor_sync(0xffffffffu, mx1, 2));

        float mn0 = fmaxf(m0, mx0), mn1 = fmaxf(m1, mx1);
        float a0 = __expf(m0 - mn0), a1 = __expf(m1 - mn1);
        float s0 = 0.f, s1 = 0.f;
#pragma unroll
        for (int in = 0; in < 8; in++) {
            sac[in][0] = __expf(sac[in][0] - mn0);
            sac[in][1] = __expf(sac[in][1] - mn0);
            sac[in][2] = __expf(sac[in][2] - mn1);
            sac[in][3] = __expf(sac[in][3] - mn1);
            s0 += sac[in][0] + sac[in][1];
            s1 += sac[in][2] + sac[in][3];
        }
        s0 += __shfl_xor_sync(0xffffffffu, s0, 1);
        s0 += __shfl_xor_sync(0xffffffffu, s0, 2);
        s1 += __shfl_xor_sync(0xffffffffu, s1, 1);
        s1 += __shfl_xor_sync(0xffffffffu, s1, 2);
        l0 = l0 * a0 + s0; m0 = mn0;
        l1 = l1 * a1 + s1; m1 = mn1;
#pragma unroll
        for (int in = 0; in < 8; in++) {
            oac[in][0] *= a0; oac[in][1] *= a0;
            oac[in][2] *= a1; oac[in][3] *= a1;
        }

        // store P to warp-private smem
#pragma unroll
        for (int in = 0; in < 8; in++) {
            *(float2*)&Pw[g * AT_W + in * 8 + 2 * ctg]       = make_float2(sac[in][0], sac[in][1]);
            *(float2*)&Pw[(g + 8) * AT_W + in * 8 + 2 * ctg] = make_float2(sac[in][2], sac[in][3]);
        }
        __syncwarp();

        // O += P @ V
#pragma unroll
        for (int kk = 0; kk < 8; kk++) {
            int kc = kk * 8;
            uint32_t pf[4];
            pf[0] = __float_as_uint(Pw[g * AT_W + kc + ctg]);
            pf[1] = __float_as_uint(Pw[(g + 8) * AT_W + kc + ctg]);
            pf[2] = __float_as_uint(Pw[g * AT_W + kc + ctg + 4]);
            pf[3] = __float_as_uint(Pw[(g + 8) * AT_W + kc + ctg + 4]);
            uint32_t bfr[8][2];
#pragma unroll
            for (int in = 0; in < 8; in++) {
                int nr = in * 8 + g;
                bfr[in][0] = __float_as_uint(Vt[(kc + ctg) * AT_W + nr]);
                bfr[in][1] = __float_as_uint(Vt[(kc + ctg + 4) * AT_W + nr]);
            }
#pragma unroll
            for (int in = 0; in < 8; in++)
                mma_tf32(oac[in], pf, bfr[in]);
        }
        __syncwarp();
    }

    // write O: row = q0 + wq*16 + g (+8), col = h*64 + in*8 + 2*ctg
    float inv0 = 1.f / l0, inv1 = 1.f / l1;
    int row0 = b * SEQ + q0 + wq * 16 + g;
#pragma unroll
    for (int in = 0; in < 8; in++) {
        int col = h * HDIM + in * 8 + 2 * ctg;
        *(float2*)&out[(size_t)row0 * CH + col] =
            make_float2(oac[in][0] * inv0, oac[in][1] * inv0);
        *(float2*)&out[(size_t)(row0 + 8) * CH + col] =
            make_float2(oac[in][2] * inv1, oac[in][3] * inv1);
    }
}

// ---------------------------------------------------------------------------
// Host: tensormap construction
// ---------------------------------------------------------------------------
typedef CUresult (*PFN_tmEncode)(
    CUtensorMap*, CUtensorMapDataType, cuuint32_t, void*,
    const cuuint64_t*, const cuuint64_t*, const cuuint32_t*, const cuuint32_t*,
    CUtensorMapInterleave, CUtensorMapSwizzle, CUtensorMapL2promotion,
    CUtensorMapFloatOOBfill);

static PFN_tmEncode get_tm_encode() {
    void* fn = nullptr;
#if CUDART_VERSION >= 12050
    cudaDriverEntryPointQueryResult qr;
    cudaGetDriverEntryPointByVersion("cuTensorMapEncodeTiled", &fn, 12000,
                                     cudaEnableDefault, &qr);
#else
    cudaDriverEntryPointQueryResult qr;
    cudaGetDriverEntryPoint("cuTensorMapEncodeTiled", &fn, cudaEnableDefault, &qr);
#endif
    return (PFN_tmEncode)fn;
}

static void make_tm(PFN_tmEncode enc, CUtensorMap* tm, const void* p, int K, int M) {
    cuuint64_t dims[2]    = {(cuuint64_t)K, (cuuint64_t)M};
    cuuint64_t strides[1] = {(cuuint64_t)K * 4};
    cuuint32_t box[2]     = {32u, 128u};
    cuuint32_t es[2]      = {1u, 1u};
    enc(tm, CU_TENSOR_MAP_DATA_TYPE_FLOAT32, 2, (void*)p, dims, strides, box, es,
        CU_TENSOR_MAP_INTERLEAVE_NONE, CU_TENSOR_MAP_SWIZZLE_128B,
        CU_TENSOR_MAP_L2_PROMOTION_L2_128B, CU_TENSOR_MAP_FLOAT_OOB_FILL_NONE);
}

// ---------------------------------------------------------------------------
// Launch
// ---------------------------------------------------------------------------
extern "C" void kernel_launch(void* const* d_in, const int* in_sizes, int n_in,
                              void* d_out, int out_size)
{
    const float* x      = (const float*)d_in[0];
    const float* c      = (const float*)d_in[1];
    const float* qkv_w  = (const float*)d_in[2];
    const float* qkv_b  = (const float*)d_in[3];
    const float* proj_w = (const float*)d_in[4];
    const float* proj_b = (const float*)d_in[5];
    const float* fc1_w  = (const float*)d_in[6];
    const float* fc1_b  = (const float*)d_in[7];
    const float* fc2_w  = (const float*)d_in[8];
    const float* fc2_b  = (const float*)d_in[9];
    const float* ada_w  = (const float*)d_in[10];
    const float* ada_b  = (const float*)d_in[11];
    float* out = (float*)d_out;

    float *p_ada, *p_h, *p_qkv, *p_att, *p_x1, *p_mlp;
    cudaGetSymbolAddress((void**)&p_ada, g_ada);
    cudaGetSymbolAddress((void**)&p_h,   g_h);
    cudaGetSymbolAddress((void**)&p_qkv, g_qkv);
    cudaGetSymbolAddress((void**)&p_att, g_att);
    cudaGetSymbolAddress((void**)&p_x1,  g_x1);
    cudaGetSymbolAddress((void**)&p_mlp, g_mlp);

    PFN_tmEncode enc = get_tm_encode();
    alignas(64) CUtensorMap tm_h, tm_att, tm_mlp, tm_qkvw, tm_projw, tm_fc1w, tm_fc2w;
    make_tm(enc, &tm_h,     p_h,    CH,    ROWS);
    make_tm(enc, &tm_att,   p_att,  CH,    ROWS);
    make_tm(enc, &tm_mlp,   p_mlp,  HFDIM, ROWS);
    make_tm(enc, &tm_qkvw,  qkv_w,  CH,    C3);
    make_tm(enc, &tm_projw, proj_w, CH,    CH);
    make_tm(enc, &tm_fc1w,  fc1_w,  CH,    HFDIM);
    make_tm(enc, &tm_fc2w,  fc2_w,  HFDIM, CH);

    cudaFuncSetAttribute(tc_gemm_kernel<0>, cudaFuncAttributeMaxDynamicSharedMemorySize, GEMM_SMEM);
    cudaFuncSetAttribute(tc_gemm_kernel<1>, cudaFuncAttributeMaxDynamicSharedMemorySize, GEMM_SMEM);
    cudaFuncSetAttribute(tc_gemm_kernel<2>, cudaFuncAttributeMaxDynamicSharedMemorySize, GEMM_SMEM);
    cudaFuncSetAttribute(attn_tc_kernel, cudaFuncAttributeMaxDynamicSharedMemorySize, ATT_SMEM);

    // 1) adaLN parameters
    ada_kernel<<<dim3(C6 / 8, BATCH), 256>>>(c, ada_w, ada_b);

    // 2) h = modulate(LN(x), sh_msa, sc_msa)
    ln_mod_kernel<<<ROWS, 256>>>(x, 0, 768, p_h);

    // 3) qkv = h @ qkv_w^T + qkv_b
    tc_gemm_kernel<0><<<dim3(C3 / 128, ROWS / 128), 288, GEMM_SMEM>>>(
        tm_h, tm_qkvw, qkv_b, nullptr, nullptr, p_qkv, C3, CH);

    // 4) attention -> g_att
    attn_tc_kernel<<<dim3(SEQ / 64, NHEAD, BATCH), 128, ATT_SMEM>>>(p_qkv, p_att);

    // 5) x1 = x + g_msa * (attn @ proj_w^T + proj_b)
    tc_gemm_kernel<2><<<dim3(CH / 128, ROWS / 128), 288, GEMM_SMEM>>>(
        tm_att, tm_projw, proj_b, x, p_ada + 1536, p_x1, CH, CH);

    // 6) h = modulate(LN(x1), sh_mlp, sc_mlp)
    ln_mod_kernel<<<ROWS, 256>>>(p_x1, 2304, 3072, p_h);

    // 7) mlp_hidden = gelu(h @ fc1_w^T + fc1_b)
    tc_gemm_kernel<1><<<dim3(HFDIM / 128, ROWS / 128), 288, GEMM_SMEM>>>(
        tm_h, tm_fc1w, fc1_b, nullptr, nullptr, p_mlp, HFDIM, CH);

    // 8) out = x1 + g_mlp * (mlp_hidden @ fc2_w^T + fc2_b)
    tc_gemm_kernel<2><<<dim3(CH / 128, ROWS / 128), 288, GEMM_SMEM>>>(
        tm_mlp, tm_fc2w, fc2_b, p_x1, p_ada + 3840, out, CH, HFDIM);
}

// round 5
// speedup vs baseline: 6.8696x; 2.1582x over previous
#include <cuda_runtime.h>
#include <cuda.h>
#include <cuda_bf16.h>
#include <math.h>
#include <stdint.h>

// Problem constants
#define BATCH 8
#define SEQ   1024
#define CH    768
#define C3    2304      // 3*CH
#define C6    4608      // 6*CH
#define HFDIM 3072      // 4*CH
#define NHEAD 12
#define HDIM  64
#define ROWS  8192      // BATCH*SEQ

// ---------------------------------------------------------------------------
// Scratch (device globals — no allocation allowed)
// ---------------------------------------------------------------------------
__device__ float g_ada[BATCH * C6];
__device__ float g_x1 [(size_t)ROWS * CH];
__device__ __nv_bfloat16 g_hb  [(size_t)ROWS * CH];
__device__ __nv_bfloat16 g_qkvh[(size_t)ROWS * C3];
__device__ __nv_bfloat16 g_attb[(size_t)ROWS * CH];
__device__ __nv_bfloat16 g_mlph[(size_t)ROWS * HFDIM];
__device__ __nv_bfloat16 g_wqkv[(size_t)C3 * CH];
__device__ __nv_bfloat16 g_wproj[(size_t)CH * CH];
__device__ __nv_bfloat16 g_wfc1[(size_t)HFDIM * CH];
__device__ __nv_bfloat16 g_wfc2[(size_t)CH * HFDIM];

// ---------------------------------------------------------------------------
// PTX helpers
// ---------------------------------------------------------------------------
__device__ __forceinline__ uint32_t smem_to_u32(const void* p) {
    uint32_t a;
    asm("{ .reg .u64 t; cvta.to.shared.u64 t, %1; cvt.u32.u64 %0, t; }"
        : "=r"(a) : "l"(p));
    return a;
}

#define MBARRIER_INIT(addr, cnt) \
    asm volatile("mbarrier.init.shared.b64 [%0], %1;" :: "r"((uint32_t)(addr)), "r"((uint32_t)(cnt)) : "memory")

#define MBARRIER_ARRIVE(addr) \
    asm volatile("mbarrier.arrive.shared.b64 _, [%0];" :: "r"((uint32_t)(addr)) : "memory")

#define MBARRIER_EXPECT_TX(addr, bytes) \
    asm volatile("mbarrier.arrive.expect_tx.shared.b64 _, [%0], %1;" :: "r"((uint32_t)(addr)), "r"((uint32_t)(bytes)) : "memory")

#define MBARRIER_WAIT_PARITY(mbar_smem_addr, phase_parity) do { \
    uint32_t _mbar = (uint32_t)(mbar_smem_addr); \
    uint32_t _parity = (uint32_t)(phase_parity); \
    uint32_t _done; \
    asm volatile( \
        "{\n\t.reg .pred p;\n\t" \
        "mbarrier.try_wait.parity.acquire.cta.shared::cta.b64 p, [%1], %2;\n\t" \
        "selp.b32 %0, 1, 0, p;\n\t}" \
        : "=r"(_done) : "r"(_mbar), "r"(_parity) : "memory"); \
    if (!_done) { \
        asm volatile( \
            "{\n\t.reg .pred P1;\n\t" \
            "WAIT_LOOP_%=:\n\t" \
            "mbarrier.try_wait.parity.acquire.cta.shared::cta.b64 P1, [%0], %1, 0x989680;\n\t" \
            "@P1 bra.uni WAIT_DONE_%=;\n\t" \
            "bra.uni WAIT_LOOP_%=;\n\t" \
            "WAIT_DONE_%=:\n\t}" \
            :: "r"(_mbar), "r"(_parity) : "memory"); \
    } \
} while(0)

#define MBARRIER_WAIT_PARITY_RELAXED(mbar_smem_addr, phase_parity) do { \
    uint32_t _mbar = (uint32_t)(mbar_smem_addr); \
    uint32_t _parity = (uint32_t)(phase_parity); \
    uint32_t _done; \
    asm volatile( \
        "{\n\t.reg .pred p;\n\t" \
        "mbarrier.try_wait.parity.relaxed.cta.shared::cta.b64 p, [%1], %2, 0x989680;\n\t" \
        "selp.b32 %0, 1, 0, p;\n\t}" \
        : "=r"(_done) : "r"(_mbar), "r"(_parity) : "memory"); \
    if (!_done) { \
        asm volatile( \
            "{\n\t.reg .pred P1;\n\t" \
            "WAIT_LOOP_%=:\n\t" \
            "mbarrier.try_wait.parity.relaxed.cta.shared::cta.b64 P1, [%0], %1, 0x989680;\n\t" \
            "@P1 bra.uni WAIT_DONE_%=;\n\t" \
            "bra.uni WAIT_LOOP_%=;\n\t" \
            "WAIT_DONE_%=:\n\t}" \
            :: "r"(_mbar), "r"(_parity) : "memory"); \
    } \
} while(0)

__device__ __forceinline__ void ldsm_x4(uint32_t* r, uint32_t addr) {
    asm volatile("ldmatrix.sync.aligned.m8n8.x4.shared.b16 {%0,%1,%2,%3}, [%4];"
        : "=r"(r[0]), "=r"(r[1]), "=r"(r[2]), "=r"(r[3]) : "r"(addr));
}
__device__ __forceinline__ void ldsm_x4_t(uint32_t* r, uint32_t addr) {
    asm volatile("ldmatrix.sync.aligned.m8n8.x4.trans.shared.b16 {%0,%1,%2,%3}, [%4];"
        : "=r"(r[0]), "=r"(r[1]), "=r"(r[2]), "=r"(r[3]) : "r"(addr));
}

__device__ __forceinline__ void mma_bf16(float* c, const uint32_t* a, uint32_t b0, uint32_t b1) {
    asm volatile(
        "mma.sync.aligned.m16n8k16.row.col.f32.bf16.bf16.f32 "
        "{%0,%1,%2,%3}, {%4,%5,%6,%7}, {%8,%9}, {%0,%1,%2,%3};"
        : "+f"(c[0]), "+f"(c[1]), "+f"(c[2]), "+f"(c[3])
        : "r"(a[0]), "r"(a[1]), "r"(a[2]), "r"(a[3]), "r"(b0), "r"(b1));
}

// pack (lo, hi) floats into bf16x2
__device__ __forceinline__ uint32_t pack_bf16(float lo, float hi) {
    uint32_t d;
    asm("cvt.rn.bf16x2.f32 %0, %1, %2;" : "=r"(d) : "f"(hi), "f"(lo));
    return d;
}

__device__ __forceinline__ void cpasync16(uint32_t dst, const void* src) {
    asm volatile("cp.async.cg.shared.global [%0], [%1], 16;" :: "r"(dst), "l"(src) : "memory");
}
#define CPASYNC_COMMIT() asm volatile("cp.async.commit_group;" ::: "memory")
#define CPASYNC_WAIT0()  asm volatile("cp.async.wait_group 0;" ::: "memory")

// ---------------------------------------------------------------------------
// 0) fp32 -> bf16 weight conversion
// ---------------------------------------------------------------------------
__global__ __launch_bounds__(256) void cvt_kernel(const float* __restrict__ src,
                                                  __nv_bfloat16* __restrict__ dst, int n4)
{
    int i = blockIdx.x * 256 + threadIdx.x;
    if (i < n4) {
        float4 v = *(const float4*)(src + (size_t)i * 4);
        uint32_t* d = (uint32_t*)dst + (size_t)i * 2;
        d[0] = pack_bf16(v.x, v.y);
        d[1] = pack_bf16(v.z, v.w);
    }
}

// ---------------------------------------------------------------------------
// 1) ada = silu(c) @ ada_w^T + ada_b      [8, 4608]
// ---------------------------------------------------------------------------
__global__ __launch_bounds__(256) void ada_kernel(
    const float* __restrict__ c,
    const float* __restrict__ ada_w,
    const float* __restrict__ ada_b)
{
    __shared__ float sc[CH];
    int b = blockIdx.y;
    for (int k = threadIdx.x; k < CH; k += 256) {
        float v = c[b * CH + k];
        sc[k] = v / (1.f + expf(-v));
    }
    __syncthreads();
    int warp = threadIdx.x >> 5, lane = threadIdx.x & 31;
    int j = blockIdx.x * 8 + warp;
    const float* w = ada_w + (size_t)j * CH;
    float s = 0.f;
    for (int k = lane; k < CH; k += 32) s += sc[k] * w[k];
#pragma unroll
    for (int o = 16; o; o >>= 1) s += __shfl_xor_sync(0xffffffffu, s, o);
    if (lane == 0) g_ada[b * C6 + j] = s + ada_b[j];
}

// ---------------------------------------------------------------------------
// 2) h = LN(x) * (1 + sc[b]) + sh[b]   -> bf16
// ---------------------------------------------------------------------------
__global__ __launch_bounds__(256) void ln_mod_kernel(
    const float* __restrict__ x, int sh_off, int sc_off,
    __nv_bfloat16* __restrict__ out)
{
    int r = blockIdx.x;
    int b = r >> 10;
    const float* xr = x + (size_t)r * CH;
    int t = threadIdx.x;
    float v[3];
    float s = 0.f, ss = 0.f;
#pragma unroll
    for (int u = 0; u < 3; u++) {
        float w = xr[t + u * 256];
        v[u] = w; s += w; ss += w * w;
    }
#pragma unroll
    for (int o = 16; o; o >>= 1) {
        s  += __shfl_xor_sync(0xffffffffu, s,  o);
        ss += __shfl_xor_sync(0xffffffffu, ss, o);
    }
    __shared__ float rs[8], rss[8];
    __shared__ float smu, srv;
    int warp = t >> 5;
    if ((t & 31) == 0) { rs[warp] = s; rss[warp] = ss; }
    __syncthreads();
    if (t == 0) {
        float ts = 0.f, tss = 0.f;
#pragma unroll
        for (int i = 0; i < 8; i++) { ts += rs[i]; tss += rss[i]; }
        float mu  = ts  * (1.f / (float)CH);
        float var = tss * (1.f / (float)CH) - mu * mu;
        smu = mu;
        srv = rsqrtf(var + 1e-6f);
    }
    __syncthreads();
    float mu = smu, rinv = srv;
    const float* sh  = g_ada + b * C6 + sh_off;
    const float* scm = g_ada + b * C6 + sc_off;
    __nv_bfloat16* orow = out + (size_t)r * CH;
#pragma unroll
    for (int u = 0; u < 3; u++) {
        int i = t + u * 256;
        orow[i] = __float2bfloat16((v[u] - mu) * rinv * (1.f + scm[i]) + sh[i]);
    }
}

// ---------------------------------------------------------------------------
// 3) TMA + mma.sync bf16 GEMM: C[M,Nc] = A[M,K] @ W[Nc,K]^T + bias (+epi)
//    128x128 tile, K-tile 64 bf16 (128B rows, SW128), 4-stage pipeline.
//    288 threads: warps 0-7 compute (64x32 each), warp 8 = TMA producer.
//    EPI: 0 = bias -> bf16; 1 = bias+GELU -> bf16; 2 = resid+gate -> fp32
// ---------------------------------------------------------------------------
#define GSTAGES 4
#define KTILE 64
#define STAGE_BYTES 32768            // A 16KB + B 16KB
#define GEMM_SMEM (1024 + GSTAGES * STAGE_BYTES)

// swizzled address in [128 rows x 128B] SW128 tile, chunk = 16B unit
__device__ __forceinline__ uint32_t gsw(uint32_t base, int row, int chunk) {
    return base + row * 128 + ((chunk ^ (row & 7)) << 4);
}

template <int EPI>
__global__ __launch_bounds__(288, 1) void tc_gemm_kernel(
    const __grid_constant__ CUtensorMap tmA,
    const __grid_constant__ CUtensorMap tmB,
    const float* __restrict__ bias,
    const float* __restrict__ resid,
    const float* __restrict__ gate,
    void* __restrict__ CoutV,
    int Nc, int K)
{
    extern __shared__ __align__(1024) char smem[];
    uint32_t sbase = smem_to_u32(smem);
    const int t = threadIdx.x, wid = t >> 5, lane = t & 31;
    const int m0 = blockIdx.y * 128, n0 = blockIdx.x * 128;
    const int KT = K / KTILE;

    const uint32_t mb_full  = sbase + 0;
    const uint32_t mb_empty = sbase + 64;
    const uint32_t stg = sbase + 1024;

    if (t == 0) {
#pragma unroll
        for (int s = 0; s < GSTAGES; s++) {
            MBARRIER_INIT(mb_full  + 8 * s, 1);
            MBARRIER_INIT(mb_empty + 8 * s, 8);
        }
    }
    __syncthreads();

    if (wid == 8) {
        if (lane == 0) {
            asm volatile("prefetch.tensormap [%0];" :: "l"(&tmA));
            asm volatile("prefetch.tensormap [%0];" :: "l"(&tmB));
            int npro = KT < GSTAGES ? KT : GSTAGES;
            for (int tt = 0; tt < npro; tt++) {
                uint32_t fm = mb_full + 8 * tt;
                uint32_t aA = stg + tt * STAGE_BYTES;
                MBARRIER_EXPECT_TX(fm, STAGE_BYTES);
                int k0 = tt * KTILE;
                asm volatile(
                    "cp.async.bulk.tensor.2d.shared::cta.global.tile.mbarrier::complete_tx::bytes "
                    "[%0], [%1, {%2, %3}], [%4];"
                    :: "r"(aA), "l"(&tmA), "r"(k0), "r"(m0), "r"(fm) : "memory");
                asm volatile(
                    "cp.async.bulk.tensor.2d.shared::cta.global.tile.mbarrier::complete_tx::bytes "
                    "[%0], [%1, {%2, %3}], [%4];"
                    :: "r"(aA + 16384), "l"(&tmB), "r"(k0), "r"(n0), "r"(fm) : "memory");
            }
            int slot = 0, ph = 0;
            for (int tt = GSTAGES; tt < KT; tt++) {
                MBARRIER_WAIT_PARITY_RELAXED(mb_empty + 8 * slot, ph);
                uint32_t fm = mb_full + 8 * slot;
                uint32_t aA = stg + slot * STAGE_BYTES;
                MBARRIER_EXPECT_TX(fm, STAGE_BYTES);
                int k0 = tt * KTILE;
                asm volatile(
                    "cp.async.bulk.tensor.2d.shared::cta.global.tile.mbarrier::complete_tx::bytes "
                    "[%0], [%1, {%2, %3}], [%4];"
                    :: "r"(aA), "l"(&tmA), "r"(k0), "r"(m0), "r"(fm) : "memory");
                asm volatile(
                    "cp.async.bulk.tensor.2d.shared::cta.global.tile.mbarrier::complete_tx::bytes "
                    "[%0], [%1, {%2, %3}], [%4];"
                    :: "r"(aA + 16384), "l"(&tmB), "r"(k0), "r"(n0), "r"(fm) : "memory");
                if (++slot == GSTAGES) { slot = 0; ph ^= 1; }
            }
        }
        return;
    }

    const int wm = wid >> 2;          // 0..1
    const int wn = wid & 3;           // 0..3
    const int g   = lane >> 2;
    const int ctg = lane & 3;
    const int lrow = (lane & 7) + 8 * ((lane >> 3) & 1);
    const int lch  = lane >> 4;

    float acc[4][4][4];
#pragma unroll
    for (int im = 0; im < 4; im++)
#pragma unroll
        for (int in = 0; in < 4; in++)
#pragma unroll
            for (int r = 0; r < 4; r++) acc[im][in][r] = 0.f;

    int slot = 0, ph = 0;
    for (int tt = 0; tt < KT; tt++) {
        MBARRIER_WAIT_PARITY(mb_full + 8 * slot, ph);
        const uint32_t At = stg + slot * STAGE_BYTES;
        const uint32_t Bt = At + 16384;

#pragma unroll
        for (int s = 0; s < 4; s++) {            // k16 steps
            const int kc = 2 * s;
            uint32_t afr[4][4];
#pragma unroll
            for (int im = 0; im < 4; im++)
                ldsm_x4(afr[im], gsw(At, wm * 64 + im * 16 + lrow, kc + lch));
            uint32_t bfr[4][2];
#pragma unroll
            for (int jn = 0; jn < 2; jn++) {
                uint32_t q[4];
                ldsm_x4(q, gsw(Bt, wn * 32 + jn * 16 + lrow, kc + lch));
                bfr[2 * jn][0]     = q[0]; bfr[2 * jn][1]     = q[2];
                bfr[2 * jn + 1][0] = q[1]; bfr[2 * jn + 1][1] = q[3];
            }
#pragma unroll
            for (int im = 0; im < 4; im++)
#pragma unroll
                for (int in = 0; in < 4; in++)
                    mma_bf16(acc[im][in], afr[im], bfr[in][0], bfr[in][1]);
        }

        if (lane == 0) MBARRIER_ARRIVE(mb_empty + 8 * slot);
        if (++slot == GSTAGES) { slot = 0; ph ^= 1; }
    }

    // epilogue
    const int bidx = m0 >> 10;
    const int mB = m0 + wm * 64;
    const int nB = n0 + wn * 32;
#pragma unroll
    for (int im = 0; im < 4; im++) {
        int r = mB + im * 16 + g;
#pragma unroll
        for (int in = 0; in < 4; in++) {
            int n = nB + in * 8 + 2 * ctg;
            float b0 = bias[n], b1 = bias[n + 1];
#pragma unroll
            for (int half = 0; half < 2; half++) {
                int m = r + half * 8;
                float v0 = acc[im][in][2 * half + 0] + b0;
                float v1 = acc[im][in][2 * half + 1] + b1;
                if (EPI == 1) {
                    v0 = 0.5f * v0 * (1.f + erff(v0 * 0.70710678118654752f));
                    v1 = 0.5f * v1 * (1.f + erff(v1 * 0.70710678118654752f));
                }
                if (EPI == 2) {
                    const float2 rr = *(const float2*)&resid[(size_t)m * Nc + n];
                    float g0 = gate[bidx * C6 + n], g1 = gate[bidx * C6 + n + 1];
                    v0 = rr.x + g0 * v0;
                    v1 = rr.y + g1 * v1;
                    *(float2*)&((float*)CoutV)[(size_t)m * Nc + n] = make_float2(v0, v1);
                } else {
                    ((uint32_t*)CoutV)[((size_t)m * Nc + n) >> 1] = pack_bf16(v0, v1);
                }
            }
        }
    }
}

// ---------------------------------------------------------------------------
// 4) bf16 flash attention with mma.sync + ldmatrix, P kept in registers.
//    CTA = 4 warps / 64 q-rows. K/V 64-row tiles double-buffered (cp.async).
//    Tiles padded to 72 bf16 (144B) rows -> conflict-free ldmatrix.
// ---------------------------------------------------------------------------
#define AT_WB 144                        // tile row stride in bytes
#define AT_TILE_B (64 * AT_WB)           // 9216 bytes per tile
#define ATT_SMEM (5 * AT_TILE_B)         // Q + 2K + 2V = 46080

__global__ __launch_bounds__(128, 3) void attn_tc_kernel(
    const __nv_bfloat16* __restrict__ qkv, __nv_bfloat16* __restrict__ out)
{
    extern __shared__ __align__(16) char as[];
    const uint32_t Qb = smem_to_u32(as);
    const uint32_t Kb = Qb + AT_TILE_B;          // 2 tiles
    const uint32_t Vb = Kb + 2 * AT_TILE_B;      // 2 tiles

    const int b = blockIdx.z, h = blockIdx.y;
    const int q0 = blockIdx.x * 64;
    const int t = threadIdx.x, wq = t >> 5, lane = t & 31;
    const int g = lane >> 2, ctg = lane & 3;
    const int lrow = (lane & 7) + 8 * ((lane >> 3) & 1);
    const int lch  = lane >> 4;

    const __nv_bfloat16* qb = qkv + (size_t)(b * SEQ) * C3 + h * HDIM;
    const __nv_bfloat16* kb = qb + CH;
    const __nv_bfloat16* vb = qb + 2 * CH;

    // K/V tile 0 + Q tile loads (cp.async, 16B = 8 bf16 chunks)
#pragma unroll
    for (int u = 0; u < 4; u++) {
        int i = t + u * 128;             // 512 chunks per tile
        int r = i >> 3, c = i & 7;
        uint32_t so = (uint32_t)(r * AT_WB + c * 16);
        cpasync16(Kb + so, kb + (size_t)r * C3 + c * 8);
        cpasync16(Vb + so, vb + (size_t)r * C3 + c * 8);
        cpasync16(Qb + so, qb + (size_t)(q0 + r) * C3 + c * 8);
    }
    CPASYNC_COMMIT();

    float m0 = -1e30f, m1 = -1e30f, l0 = 0.f, l1 = 0.f;
    float oac[8][4];
#pragma unroll
    for (int in = 0; in < 8; in++)
#pragma unroll
        for (int r = 0; r < 4; r++) oac[in][r] = 0.f;

    uint32_t qf[4][4];

    for (int kt = 0; kt < 16; kt++) {
        CPASYNC_WAIT0();
        __syncthreads();
        if (kt == 0) {
            // preload Q fragments via ldmatrix
#pragma unroll
            for (int kk = 0; kk < 4; kk++)
                ldsm_x4(qf[kk], Qb + (wq * 16 + lrow) * AT_WB + (2 * kk + lch) * 16);
        }
        // prefetch next K/V tile
        if (kt + 1 < 16) {
            int nb = (kt + 1) & 1;
            int kr0 = (kt + 1) * 64;
            uint32_t kd = Kb + nb * AT_TILE_B;
            uint32_t vd = Vb + nb * AT_TILE_B;
#pragma unroll
            for (int u = 0; u < 4; u++) {
                int i = t + u * 128;
                int r = i >> 3, c = i & 7;
                uint32_t so = (uint32_t)(r * AT_WB + c * 16);
                cpasync16(kd + so, kb + (size_t)(kr0 + r) * C3 + c * 8);
                cpasync16(vd + so, vb + (size_t)(kr0 + r) * C3 + c * 8);
            }
            CPASYNC_COMMIT();
        }

        const uint32_t Kt = Kb + (kt & 1) * AT_TILE_B;
        const uint32_t Vt = Vb + (kt & 1) * AT_TILE_B;

        // S = Q @ K^T
        float sac[8][4];
#pragma unroll
        for (int in = 0; in < 8; in++)
#pragma unroll
            for (int r = 0; r < 4; r++) sac[in][r] = 0.f;

#pragma unroll
        for (int kk = 0; kk < 4; kk++) {
            const int kc = 2 * kk;
#pragma unroll
            for (int jn = 0; jn < 4; jn++) {
                uint32_t q[4];
                ldsm_x4(q, Kt + (jn * 16 + lrow) * AT_WB + (kc + lch) * 16);
                mma_bf16(sac[2 * jn],     qf[kk], q[0], q[2]);
                mma_bf16(sac[2 * jn + 1], qf[kk], q[1], q[3]);
            }
        }
        // scale
#pragma unroll
        for (int in = 0; in < 8; in++)
#pragma unroll
            for (int r = 0; r < 4; r++) sac[in][r] *= 0.125f;

        // online softmax (rows g, g+8)
        float mx0 = -1e30f, mx1 = -1e30f;
#pragma unroll
        for (int in = 0; in < 8; in++) {
            mx0 = fmaxf(mx0, fmaxf(sac[in][0], sac[in][1]));
            mx1 = fmaxf(mx1, fmaxf(sac[in][2], sac[in][3]));
        }
        mx0 = fmaxf(mx0, __shfl_xor_sync(0xffffffffu, mx0, 1));
        mx0 = fmaxf(mx0, __shfl_xor_sync(0xffffffffu, mx0, 2));
        mx1 = fmaxf(mx1, __shfl_xor_sync(0xffffffffu, mx1, 1));
        mx1 = fmaxf(mx1, __shfl_xor_sync(0xffffffffu, mx1, 2));

        float mn0 = fmaxf(m0, mx0), mn1 = fmaxf(m1, mx1);
        float a0 = __expf(m0 - mn0), a1 = __expf(m1 - mn1);
        float s0 = 0.f, s1 = 0.f;
#pragma unroll
        for (int in = 0; in < 8; in++) {
            sac[in][0] = __expf(sac[in][0] - mn0);
            sac[in][1] = __expf(sac[in][1] - mn0);
            sac[in][2] = __expf(sac[in][2] - mn1);
            sac[in][3] = __expf(sac[in][3] - mn1);
            s0 += sac[in][0] + sac[in][1];
            s1 += sac[in][2] + sac[in][3];
        }
        s0 += __shfl_xor_sync(0xffffffffu, s0, 1);
        s0 += __shfl_xor_sync(0xffffffffu, s0, 2);
        s1 += __shfl_xor_sync(0xffffffffu, s1, 1);
        s1 += __shfl_xor_sync(0xffffffffu, s1, 2);
        l0 = l0 * a0 + s0; m0 = mn0;
        l1 = l1 * a1 + s1; m1 = mn1;
#pragma unroll
        for (int in = 0; in < 8; in++) {
            oac[in][0] *= a0; oac[in][1] *= a0;
            oac[in][2] *= a1; oac[in][3] *= a1;
        }

        // O += P @ V   (P packed to bf16 in registers, no smem round-trip)
#pragma unroll
        for (int kk = 0; kk < 4; kk++) {
            uint32_t pf[4];
            pf[0] = pack_bf16(sac[2 * kk][0],     sac[2 * kk][1]);
            pf[1] = pack_bf16(sac[2 * kk][2],     sac[2 * kk][3]);
            pf[2] = pack_bf16(sac[2 * kk + 1][0], sac[2 * kk + 1][1]);
            pf[3] = pack_bf16(sac[2 * kk + 1][2], sac[2 * kk + 1][3]);
            const int vrow = 16 * kk + (lane & 7) + 8 * (lane >> 4);
#pragma unroll
            for (int jn = 0; jn < 4; jn++) {
                uint32_t q[4];
                ldsm_x4_t(q, Vt + vrow * AT_WB + (2 * jn + ((lane >> 3) & 1)) * 16);
                mma_bf16(oac[2 * jn],     pf, q[0], q[2]);
                mma_bf16(oac[2 * jn + 1], pf, q[1], q[3]);
            }
        }
        __syncthreads();
    }

    // write O (bf16)
    float inv0 = 1.f / l0, inv1 = 1.f / l1;
    int row0 = b * SEQ + q0 + wq * 16 + g;
    uint32_t* o32 = (uint32_t*)out;
#pragma unroll
    for (int in = 0; in < 8; in++) {
        int col = h * HDIM + in * 8 + 2 * ctg;
        o32[((size_t)row0 * CH + col) >> 1] =
            pack_bf16(oac[in][0] * inv0, oac[in][1] * inv0);
        o32[((size_t)(row0 + 8) * CH + col) >> 1] =
            pack_bf16(oac[in][2] * inv1, oac[in][3] * inv1);
    }
}

// ---------------------------------------------------------------------------
// Host: tensormap construction
// ---------------------------------------------------------------------------
typedef CUresult (*PFN_tmEncode)(
    CUtensorMap*, CUtensorMapDataType, cuuint32_t, void*,
    const cuuint64_t*, const cuuint64_t*, const cuuint32_t*, const cuuint32_t*,
    CUtensorMapInterleave, CUtensorMapSwizzle, CUtensorMapL2promotion,
    CUtensorMapFloatOOBfill);

static PFN_tmEncode get_tm_encode() {
    void* fn = nullptr;
#if CUDART_VERSION >= 12050
    cudaDriverEntryPointQueryResult qr;
    cudaGetDriverEntryPointByVersion("cuTensorMapEncodeTiled", &fn, 12000,
                                     cudaEnableDefault, &qr);
#else
    cudaDriverEntryPointQueryResult qr;
    cudaGetDriverEntryPoint("cuTensorMapEncodeTiled", &fn, cudaEnableDefault, &qr);
#endif
    return (PFN_tmEncode)fn;
}

static void make_tm_bf16(PFN_tmEncode enc, CUtensorMap* tm, const void* p, int K, int M) {
    cuuint64_t dims[2]    = {(cuuint64_t)K, (cuuint64_t)M};
    cuuint64_t strides[1] = {(cuuint64_t)K * 2};
    cuuint32_t box[2]     = {64u, 128u};
    cuuint32_t es[2]      = {1u, 1u};
    enc(tm, CU_TENSOR_MAP_DATA_TYPE_BFLOAT16, 2, (void*)p, dims, strides, box, es,
        CU_TENSOR_MAP_INTERLEAVE_NONE, CU_TENSOR_MAP_SWIZZLE_128B,
        CU_TENSOR_MAP_L2_PROMOTION_L2_128B, CU_TENSOR_MAP_FLOAT_OOB_FILL_NONE);
}

// ---------------------------------------------------------------------------
// Launch
// ---------------------------------------------------------------------------
extern "C" void kernel_launch(void* const* d_in, const int* in_sizes, int n_in,
                              void* d_out, int out_size)
{
    const float* x      = (const float*)d_in[0];
    const float* c      = (const float*)d_in[1];
    const float* qkv_w  = (const float*)d_in[2];
    const float* qkv_b  = (const float*)d_in[3];
    const float* proj_w = (const float*)d_in[4];
    const float* proj_b = (const float*)d_in[5];
    const float* fc1_w  = (const float*)d_in[6];
    const float* fc1_b  = (const float*)d_in[7];
    const float* fc2_w  = (const float*)d_in[8];
    const float* fc2_b  = (const float*)d_in[9];
    const float* ada_w  = (const float*)d_in[10];
    const float* ada_b  = (const float*)d_in[11];
    float* out = (float*)d_out;

    float *p_ada, *p_x1;
    __nv_bfloat16 *p_hb, *p_qkvh, *p_attb, *p_mlph, *p_wqkv, *p_wproj, *p_wfc1, *p_wfc2;
    cudaGetSymbolAddress((void**)&p_ada,   g_ada);
    cudaGetSymbolAddress((void**)&p_x1,    g_x1);
    cudaGetSymbolAddress((void**)&p_hb,    g_hb);
    cudaGetSymbolAddress((void**)&p_qkvh,  g_qkvh);
    cudaGetSymbolAddress((void**)&p_attb,  g_attb);
    cudaGetSymbolAddress((void**)&p_mlph,  g_mlph);
    cudaGetSymbolAddress((void**)&p_wqkv,  g_wqkv);
    cudaGetSymbolAddress((void**)&p_wproj, g_wproj);
    cudaGetSymbolAddress((void**)&p_wfc1,  g_wfc1);
    cudaGetSymbolAddress((void**)&p_wfc2,  g_wfc2);

    PFN_tmEncode enc = get_tm_encode();
    alignas(64) CUtensorMap tm_h, tm_att, tm_mlp, tm_qkvw, tm_projw, tm_fc1w, tm_fc2w;
    make_tm_bf16(enc, &tm_h,     p_hb,    CH,    ROWS);
    make_tm_bf16(enc, &tm_att,   p_attb,  CH,    ROWS);
    make_tm_bf16(enc, &tm_mlp,   p_mlph,  HFDIM, ROWS);
    make_tm_bf16(enc, &tm_qkvw,  p_wqkv,  CH,    C3);
    make_tm_bf16(enc, &tm_projw, p_wproj, CH,    CH);
    make_tm_bf16(enc, &tm_fc1w,  p_wfc1,  CH,    HFDIM);
    make_tm_bf16(enc, &tm_fc2w,  p_wfc2,  HFDIM, CH);

    cudaFuncSetAttribute(tc_gemm_kernel<0>, cudaFuncAttributeMaxDynamicSharedMemorySize, GEMM_SMEM);
    cudaFuncSetAttribute(tc_gemm_kernel<1>, cudaFuncAttributeMaxDynamicSharedMemorySize, GEMM_SMEM);
    cudaFuncSetAttribute(tc_gemm_kernel<2>, cudaFuncAttributeMaxDynamicSharedMemorySize, GEMM_SMEM);
    cudaFuncSetAttribute(attn_tc_kernel, cudaFuncAttributeMaxDynamicSharedMemorySize, ATT_SMEM);

    // 0) weight conversion fp32 -> bf16
    cvt_kernel<<<(C3 * CH / 4 + 255) / 256, 256>>>(qkv_w, p_wqkv, C3 * CH / 4);
    cvt_kernel<<<(CH * CH / 4 + 255) / 256, 256>>>(proj_w, p_wproj, CH * CH / 4);
    cvt_kernel<<<(HFDIM * CH / 4 + 255) / 256, 256>>>(fc1_w, p_wfc1, HFDIM * CH / 4);
    cvt_kernel<<<(CH * HFDIM / 4 + 255) / 256, 256>>>(fc2_w, p_wfc2, CH * HFDIM / 4);

    // 1) adaLN parameters
    ada_kernel<<<dim3(C6 / 8, BATCH), 256>>>(c, ada_w, ada_b);

    // 2) h = modulate(LN(x), sh_msa, sc_msa) -> bf16
    ln_mod_kernel<<<ROWS, 256>>>(x, 0, 768, p_hb);

    // 3) qkv = h @ qkv_w^T + qkv_b -> bf16
    tc_gemm_kernel<0><<<dim3(C3 / 128, ROWS / 128), 288, GEMM_SMEM>>>(
        tm_h, tm_qkvw, qkv_b, nullptr, nullptr, p_qkvh, C3, CH);

    // 4) attention -> bf16
    attn_tc_kernel<<<dim3(SEQ / 64, NHEAD, BATCH), 128, ATT_SMEM>>>(p_qkvh, p_attb);

    // 5) x1 = x + g_msa * (attn @ proj_w^T + proj_b) -> fp32
    tc_gemm_kernel<2><<<dim3(CH / 128, ROWS / 128), 288, GEMM_SMEM>>>(
        tm_att, tm_projw, proj_b, x, p_ada + 1536, p_x1, CH, CH);

    // 6) h = modulate(LN(x1), sh_mlp, sc_mlp) -> bf16
    ln_mod_kernel<<<ROWS, 256>>>(p_x1, 2304, 3072, p_hb);

    // 7) mlp_hidden = gelu(h @ fc1_w^T + fc1_b) -> bf16
    tc_gemm_kernel<1><<<dim3(HFDIM / 128, ROWS / 128), 288, GEMM_SMEM>>>(
        tm_h, tm_fc1w, fc1_b, nullptr, nullptr, p_mlph, HFDIM, CH);

    // 8) out = x1 + g_mlp * (mlp_hidden @ fc2_w^T + fc2_b) -> fp32
    tc_gemm_kernel<2><<<dim3(CH / 128, ROWS / 128), 288, GEMM_SMEM>>>(
        tm_mlp, tm_fc2w, fc2_b, p_x1, p_ada + 3840, out, CH, HFDIM);
}